// round 1
// baseline (speedup 1.0000x reference)
#include <cuda_runtime.h>
#include <cuda_bf16.h>
#include <math.h>
#include <stdint.h>

// Problem constants
#define NN 4096
#define DD 256
#define HH 8
#define HD 32
#define EE 65536
#define NWORDS 128          // 4096 bits / 32
#define SCALE 0.17677669529663687f  // 1/sqrt(32)

// -------- scratch (no allocations allowed) --------
__device__ uint32_t g_adj[NN * NWORDS];
__device__ uint32_t g_mask[NN * NWORDS];
__device__ float g_Q[NN * DD];
__device__ float g_K[NN * DD];
__device__ float g_V[NN * DD];
__device__ float g_att[NN * DD];
__device__ float g_tmp[NN * DD];

// ============ 1. adjacency init: zero + self loops ============
__global__ void adj_init_kernel() {
    int idx = blockIdx.x * blockDim.x + threadIdx.x;  // over NN*NWORDS
    int n = idx >> 7;
    int w = idx & 127;
    uint32_t v = 0;
    if (w == (n >> 5)) v = 1u << (n & 31);
    g_adj[idx] = v;
}

// ============ 2. scatter edges (undirected) ============
__global__ void edge_kernel(const int* __restrict__ ei) {
    int e = blockIdx.x * blockDim.x + threadIdx.x;
    if (e >= EE) return;
    int s = ei[e];
    int d = ei[EE + e];
    atomicOr(&g_adj[s * NWORDS + (d >> 5)], 1u << (d & 31));
    atomicOr(&g_adj[d * NWORDS + (s >> 5)], 1u << (s & 31));
}

// ============ 3. reach-2 mask: row n = OR of adj rows of n's neighbors ====
__global__ void mask_kernel() {
    int n = blockIdx.x;
    int tid = threadIdx.x;  // 128 threads, one word each
    __shared__ uint32_t row[NWORDS];
    row[tid] = g_adj[n * NWORDS + tid];
    __syncthreads();
    uint32_t acc = 0;
    for (int w = 0; w < NWORDS; w++) {
        uint32_t bits = row[w];
        while (bits) {
            int b = __ffs(bits) - 1;
            bits &= bits - 1;
            int k = (w << 5) + b;
            acc |= g_adj[k * NWORDS + tid];  // coalesced across threads
        }
    }
    g_mask[n * NWORDS + tid] = acc;
}

// ============ 4. tiled GEMM + bias: C[M,Nc] = A[M,Kc]@B[Kc,Nc] + bias =====
#define GBM 64
#define GBN 64
#define GBK 16
__global__ void gemm_bias_kernel(const float* __restrict__ A,
                                 const float* __restrict__ B,
                                 const float* __restrict__ bias,
                                 float* __restrict__ C,
                                 int M, int Nc, int Kc) {
    __shared__ float As[GBK][GBM + 1];
    __shared__ float Bs[GBK][GBN];
    int tid = threadIdx.x;  // 256
    int m0 = blockIdx.y * GBM;
    int n0 = blockIdx.x * GBN;
    int ty = tid >> 4, tx = tid & 15;
    float c[4][4] = {};
    for (int kk = 0; kk < Kc; kk += GBK) {
#pragma unroll
        for (int t = 0; t < 4; t++) {
            int l = tid + t * 256;      // 1024 elems
            int m = l >> 4, k = l & 15;
            As[k][m] = A[(m0 + m) * Kc + kk + k];
        }
#pragma unroll
        for (int t = 0; t < 4; t++) {
            int l = tid + t * 256;
            int k = l >> 6, n = l & 63;
            Bs[k][n] = B[(kk + k) * Nc + n0 + n];
        }
        __syncthreads();
#pragma unroll
        for (int k = 0; k < GBK; k++) {
            float a[4], b[4];
#pragma unroll
            for (int i = 0; i < 4; i++) a[i] = As[k][ty * 4 + i];
#pragma unroll
            for (int j = 0; j < 4; j++) b[j] = Bs[k][tx * 4 + j];
#pragma unroll
            for (int i = 0; i < 4; i++)
#pragma unroll
                for (int j = 0; j < 4; j++) c[i][j] += a[i] * b[j];
        }
        __syncthreads();
    }
#pragma unroll
    for (int i = 0; i < 4; i++) {
        int m = m0 + ty * 4 + i;
#pragma unroll
        for (int j = 0; j < 4; j++) {
            int n = n0 + tx * 4 + j;
            C[m * Nc + n] = c[i][j] + bias[n];
        }
    }
}

// ============ 5. masked flash attention (fp32 SIMT) ============
// Block: 256 threads, 64 queries, one head. Iterates 64-key tiles.
#define BQ 64
#define BKT 64
__global__ void attn_kernel(const float* __restrict__ Q,
                            const float* __restrict__ K,
                            const float* __restrict__ V,
                            float* __restrict__ Out) {
    int h = blockIdx.y;
    int q0 = blockIdx.x * BQ;
    int tid = threadIdx.x;

    __shared__ float Qs[BQ][HD + 1];       // padded vs stride-32 conflicts
    __shared__ float Ks[BKT][HD];
    __shared__ float Vs[BKT][HD];
    __shared__ float Ss[BQ][BKT + 1];      // padded vs stride-64 conflicts
    __shared__ float pm[4][BQ];
    __shared__ float ps[4][BQ];
    __shared__ float m_s[BQ], l_s[BQ], alpha_s[BQ];
    __shared__ uint32_t mw[BQ][2];

    // load Q tile once
    for (int i = tid; i < BQ * HD; i += 256) {
        int q = i >> 5, d = i & 31;
        Qs[q][d] = Q[(q0 + q) * DD + h * HD + d];
    }
    int q  = tid & 63;        // my query
    int g  = tid >> 6;        // group 0..3
    int j0 = g * 16;          // my 16 score columns
    int d0 = g * 8;           // my 8 output dims
    float acc[8];
#pragma unroll
    for (int i = 0; i < 8; i++) acc[i] = 0.f;
    if (tid < BQ) { m_s[tid] = -INFINITY; l_s[tid] = 0.f; }
    __syncthreads();

    for (int k0 = 0; k0 < NN; k0 += BKT) {
        // load K/V tiles + mask words
        for (int i = tid; i < BKT * HD; i += 256) {
            int r = i >> 5, d = i & 31;
            Ks[r][d] = K[(k0 + r) * DD + h * HD + d];
            Vs[r][d] = V[(k0 + r) * DD + h * HD + d];
        }
        if (tid < BQ * 2) {
            int r = tid >> 1, w = tid & 1;
            mw[r][w] = g_mask[(q0 + r) * NWORDS + (k0 >> 5) + w];
        }
        __syncthreads();

        // scores for my 16 columns
        float sv[16];
        float pmax = -INFINITY;
#pragma unroll
        for (int jj = 0; jj < 16; jj++) {
            int j = j0 + jj;
            float s = 0.f;
#pragma unroll
            for (int d = 0; d < HD; d++) s += Qs[q][d] * Ks[j][d];
            s *= SCALE;
            uint32_t bit = (mw[q][j >> 5] >> (j & 31)) & 1u;
            s = bit ? s : -1e9f;
            sv[jj] = s;
            pmax = fmaxf(pmax, s);
        }
        pm[g][q] = pmax;
        __syncthreads();

        if (tid < BQ) {
            float mo = m_s[tid];
            float mn = fmaxf(fmaxf(pm[0][tid], pm[1][tid]),
                             fmaxf(pm[2][tid], pm[3][tid]));
            mn = fmaxf(mo, mn);
            m_s[tid] = mn;
            alpha_s[tid] = __expf(mo - mn);  // exp(-inf)=0 first time
        }
        __syncthreads();

        float mn = m_s[q];
        float psum = 0.f;
#pragma unroll
        for (int jj = 0; jj < 16; jj++) {
            float p = __expf(sv[jj] - mn);
            Ss[q][j0 + jj] = p;
            psum += p;
        }
        ps[g][q] = psum;
        __syncthreads();

        if (tid < BQ)
            l_s[tid] = l_s[tid] * alpha_s[tid] +
                       ps[0][tid] + ps[1][tid] + ps[2][tid] + ps[3][tid];

        float alpha = alpha_s[q];
#pragma unroll
        for (int i = 0; i < 8; i++) acc[i] *= alpha;
        for (int j = 0; j < BKT; j++) {
            float p = Ss[q][j];
#pragma unroll
            for (int i = 0; i < 8; i++) acc[i] += p * Vs[j][d0 + i];
        }
        __syncthreads();
    }

    float inv_l = 1.f / l_s[q];
#pragma unroll
    for (int i = 0; i < 8; i++)
        Out[(q0 + q) * DD + h * HD + d0 + i] = acc[i] * inv_l;
}

// ============ 6. residual + LayerNorm ============
__global__ void ln_kernel(const float* __restrict__ tmp,
                          const float* __restrict__ x,
                          const float* __restrict__ w,
                          const float* __restrict__ b,
                          float* __restrict__ out) {
    int n = blockIdx.x;
    int tid = threadIdx.x;  // 256 == DD
    float v = tmp[n * DD + tid] + x[n * DD + tid];
    __shared__ float s1[256], s2[256];
    s1[tid] = v;
    s2[tid] = v * v;
    __syncthreads();
    for (int st = 128; st > 0; st >>= 1) {
        if (tid < st) { s1[tid] += s1[tid + st]; s2[tid] += s2[tid + st]; }
        __syncthreads();
    }
    float mu  = s1[0] * (1.f / 256.f);
    float var = s2[0] * (1.f / 256.f) - mu * mu;
    float inv = rsqrtf(var + 1e-5f);
    out[n * DD + tid] = (v - mu) * inv * w[tid] + b[tid];
}

// ============ launch ============
extern "C" void kernel_launch(void* const* d_in, const int* in_sizes, int n_in,
                              void* d_out, int out_size) {
    const float* x    = (const float*)d_in[0];
    const int*   ei   = (const int*)d_in[1];
    const float* Wq   = (const float*)d_in[2];
    const float* bq   = (const float*)d_in[3];
    const float* Wk   = (const float*)d_in[4];
    const float* bk   = (const float*)d_in[5];
    const float* Wv   = (const float*)d_in[6];
    const float* bv   = (const float*)d_in[7];
    const float* Wo   = (const float*)d_in[8];
    const float* bo   = (const float*)d_in[9];
    const float* lnw  = (const float*)d_in[10];
    const float* lnb  = (const float*)d_in[11];
    float* out = (float*)d_out;

    float *gQ, *gK, *gV, *gA, *gT;
    cudaGetSymbolAddress((void**)&gQ, g_Q);
    cudaGetSymbolAddress((void**)&gK, g_K);
    cudaGetSymbolAddress((void**)&gV, g_V);
    cudaGetSymbolAddress((void**)&gA, g_att);
    cudaGetSymbolAddress((void**)&gT, g_tmp);

    // mask pipeline
    adj_init_kernel<<<(NN * NWORDS) / 256, 256>>>();
    edge_kernel<<<EE / 256, 256>>>(ei);
    mask_kernel<<<NN, NWORDS>>>();

    // QKV projections
    dim3 ggrid(DD / GBN, NN / GBM);
    gemm_bias_kernel<<<ggrid, 256>>>(x, Wq, bq, gQ, NN, DD, DD);
    gemm_bias_kernel<<<ggrid, 256>>>(x, Wk, bk, gK, NN, DD, DD);
    gemm_bias_kernel<<<ggrid, 256>>>(x, Wv, bv, gV, NN, DD, DD);

    // attention
    attn_kernel<<<dim3(NN / BQ, HH), 256>>>(gQ, gK, gV, gA);

    // output projection + residual + LN
    gemm_bias_kernel<<<ggrid, 256>>>(gA, Wo, bo, gT, NN, DD, DD);
    ln_kernel<<<NN, 256>>>(gT, x, lnw, lnb, out);
}

// round 3
// speedup vs baseline: 7.5584x; 7.5584x over previous
#include <cuda_runtime.h>
#include <cuda_bf16.h>
#include <math.h>
#include <stdint.h>

// ---------------- problem constants ----------------
#define NN 4096
#define DD 256
#define HH 8
#define HD 32
#define EE 65536
#define NWORDS 128
// (1/sqrt(32)) * log2(e): folded into Q so softmax weight = exp2(S)
#define QSCALE 0.25503486f

// ---------------- scratch globals (no allocs allowed) ----------------
__device__ uint32_t g_adj[NN * NWORDS];
__device__ uint32_t g_mask[NN * NWORDS];
__device__ __nv_bfloat16 g_Qb[NN * DD];   // pre-scaled by QSCALE
__device__ __nv_bfloat16 g_Kb[NN * DD];
__device__ __nv_bfloat16 g_Vb[NN * DD];
__device__ float g_att[NN * DD];
__device__ float g_tmp[NN * DD];

// ---------------- PTX helpers ----------------
__device__ __forceinline__ uint32_t smem_u32(const void* p) {
    uint32_t a;
    asm("{ .reg .u64 t; cvta.to.shared.u64 t, %1; cvt.u32.u64 %0, t; }"
        : "=r"(a) : "l"(p));
    return a;
}
__device__ __forceinline__ float ex2f(float x) {
    float y; asm("ex2.approx.ftz.f32 %0, %1;" : "=f"(y) : "f"(x)); return y;
}
__device__ __forceinline__ uint32_t pack_bf16x2(float lo, float hi) {
    uint32_t r;
    asm("cvt.rn.bf16x2.f32 %0, %1, %2;" : "=r"(r) : "f"(hi), "f"(lo));
    return r;
}
__device__ __forceinline__ void ldsm_x4(uint32_t* r, uint32_t addr) {
    asm volatile("ldmatrix.sync.aligned.m8n8.x4.shared.b16 {%0,%1,%2,%3}, [%4];"
        : "=r"(r[0]), "=r"(r[1]), "=r"(r[2]), "=r"(r[3]) : "r"(addr));
}
__device__ __forceinline__ void ldsm_x4_t(uint32_t* r, uint32_t addr) {
    asm volatile("ldmatrix.sync.aligned.m8n8.x4.trans.shared.b16 {%0,%1,%2,%3}, [%4];"
        : "=r"(r[0]), "=r"(r[1]), "=r"(r[2]), "=r"(r[3]) : "r"(addr));
}
__device__ __forceinline__ void mma_bf16(float* c, const uint32_t* a, const uint32_t* b) {
    asm volatile(
        "mma.sync.aligned.m16n8k16.row.col.f32.bf16.bf16.f32 "
        "{%0,%1,%2,%3}, {%4,%5,%6,%7}, {%8,%9}, {%0,%1,%2,%3};"
        : "+f"(c[0]), "+f"(c[1]), "+f"(c[2]), "+f"(c[3])
        : "r"(a[0]), "r"(a[1]), "r"(a[2]), "r"(a[3]), "r"(b[0]), "r"(b[1]));
}
__device__ __forceinline__ void cp16(uint32_t dst, const void* src) {
    asm volatile("cp.async.cg.shared.global [%0], [%1], 16;" :: "r"(dst), "l"(src));
}
#define CP_COMMIT() asm volatile("cp.async.commit_group;" ::: "memory")
#define CP_WAIT(n)  asm volatile("cp.async.wait_group %0;" :: "n"(n) : "memory")

// ================= 1. adjacency init (zero + self loops) =================
__global__ void adj_init_kernel() {
    int idx = blockIdx.x * blockDim.x + threadIdx.x;
    int n = idx >> 7, w = idx & 127;
    uint32_t v = 0;
    if (w == (n >> 5)) v = 1u << (n & 31);
    g_adj[idx] = v;
}

// ================= 2. scatter edges (undirected) =================
__global__ void edge_kernel(const int* __restrict__ ei) {
    int e = blockIdx.x * blockDim.x + threadIdx.x;
    if (e >= EE) return;
    int s = ei[e], d = ei[EE + e];
    atomicOr(&g_adj[s * NWORDS + (d >> 5)], 1u << (d & 31));
    atomicOr(&g_adj[d * NWORDS + (s >> 5)], 1u << (s & 31));
}

// ================= 3. reach-2 mask =================
__global__ void mask_kernel() {
    int n = blockIdx.x;
    int tid = threadIdx.x;  // 128
    __shared__ uint32_t row[NWORDS];
    row[tid] = g_adj[n * NWORDS + tid];
    __syncthreads();
    uint32_t acc = 0;
    for (int w = 0; w < NWORDS; w++) {
        uint32_t bits = row[w];
        while (bits) {
            int b = __ffs(bits) - 1;
            bits &= bits - 1;
            acc |= g_adj[((w << 5) + b) * NWORDS + tid];
        }
    }
    g_mask[n * NWORDS + tid] = acc;
}

// ================= 4a. fused QKV GEMM (fp32 in, bf16 out) =================
#define GBM 64
#define GBN 64
#define GBK 16
__global__ void qkv_kernel(const float* __restrict__ x,
                           const float* __restrict__ Wq, const float* __restrict__ bq,
                           const float* __restrict__ Wk, const float* __restrict__ bk,
                           const float* __restrict__ Wv, const float* __restrict__ bv) {
    const float* B;
    const float* bias;
    __nv_bfloat16* C;
    float scale = 1.f;
    if (blockIdx.z == 0)      { B = Wq; bias = bq; C = g_Qb; scale = QSCALE; }
    else if (blockIdx.z == 1) { B = Wk; bias = bk; C = g_Kb; }
    else                      { B = Wv; bias = bv; C = g_Vb; }

    __shared__ float As[GBK][GBM + 1];
    __shared__ float Bs[GBK][GBN];
    int tid = threadIdx.x;
    int m0 = blockIdx.y * GBM;
    int n0 = blockIdx.x * GBN;
    int ty = tid >> 4, tx = tid & 15;
    float c[4][4] = {};
    for (int kk = 0; kk < DD; kk += GBK) {
#pragma unroll
        for (int t = 0; t < 4; t++) {
            int l = tid + t * 256;
            int m = l >> 4, k = l & 15;
            As[k][m] = x[(m0 + m) * DD + kk + k];
        }
#pragma unroll
        for (int t = 0; t < 4; t++) {
            int l = tid + t * 256;
            int k = l >> 6, n = l & 63;
            Bs[k][n] = B[(kk + k) * DD + n0 + n];
        }
        __syncthreads();
#pragma unroll
        for (int k = 0; k < GBK; k++) {
            float a[4], b[4];
#pragma unroll
            for (int i = 0; i < 4; i++) a[i] = As[k][ty * 4 + i];
#pragma unroll
            for (int j = 0; j < 4; j++) b[j] = Bs[k][tx * 4 + j];
#pragma unroll
            for (int i = 0; i < 4; i++)
#pragma unroll
                for (int j = 0; j < 4; j++) c[i][j] += a[i] * b[j];
        }
        __syncthreads();
    }
#pragma unroll
    for (int i = 0; i < 4; i++) {
        int m = m0 + ty * 4 + i;
#pragma unroll
        for (int j = 0; j < 4; j++) {
            int n = n0 + tx * 4 + j;
            C[m * DD + n] = __float2bfloat16((c[i][j] + bias[n]) * scale);
        }
    }
}

// ================= 4b. fp32 GEMM + bias (Wo projection) =================
__global__ void gemm_bias_kernel(const float* __restrict__ A,
                                 const float* __restrict__ B,
                                 const float* __restrict__ bias,
                                 float* __restrict__ C) {
    __shared__ float As[GBK][GBM + 1];
    __shared__ float Bs[GBK][GBN];
    int tid = threadIdx.x;
    int m0 = blockIdx.y * GBM;
    int n0 = blockIdx.x * GBN;
    int ty = tid >> 4, tx = tid & 15;
    float c[4][4] = {};
    for (int kk = 0; kk < DD; kk += GBK) {
#pragma unroll
        for (int t = 0; t < 4; t++) {
            int l = tid + t * 256;
            int m = l >> 4, k = l & 15;
            As[k][m] = A[(m0 + m) * DD + kk + k];
        }
#pragma unroll
        for (int t = 0; t < 4; t++) {
            int l = tid + t * 256;
            int k = l >> 6, n = l & 63;
            Bs[k][n] = B[(kk + k) * DD + n0 + n];
        }
        __syncthreads();
#pragma unroll
        for (int k = 0; k < GBK; k++) {
            float a[4], b[4];
#pragma unroll
            for (int i = 0; i < 4; i++) a[i] = As[k][ty * 4 + i];
#pragma unroll
            for (int j = 0; j < 4; j++) b[j] = Bs[k][tx * 4 + j];
#pragma unroll
            for (int i = 0; i < 4; i++)
#pragma unroll
                for (int j = 0; j < 4; j++) c[i][j] += a[i] * b[j];
        }
        __syncthreads();
    }
#pragma unroll
    for (int i = 0; i < 4; i++) {
        int m = m0 + ty * 4 + i;
#pragma unroll
        for (int j = 0; j < 4; j++) {
            int n = n0 + tx * 4 + j;
            C[m * DD + n] = c[i][j] + bias[n];
        }
    }
}

// ================= 5. mma.sync attention =================
// CTA: 128 threads (4 warps), 64 queries, one head. 32 kv tiles of 128 keys.
// Smem rows padded to 80B -> conflict-free ldmatrix (bank stride 20 mod 32).
#define RS 40   // row stride in bf16 units (80 bytes)

struct AttnSmem {
    __nv_bfloat16 Qs[64 * RS];          // 5120 B
    __nv_bfloat16 Ks[2][128 * RS];      // 2 x 10240 B
    __nv_bfloat16 Vs[2][128 * RS];      // 2 x 10240 B
    uint32_t msk[2][64][4];             // 2 x 1024 B
};

__global__ void __launch_bounds__(128, 3) attn_kernel() {
    __shared__ AttnSmem sm;
    const int tid = threadIdx.x;
    const int wid = tid >> 5;
    const int lane = tid & 31;
    const int h = blockIdx.y;
    const int q0 = blockIdx.x * 64;

    const uint32_t s_q = smem_u32(sm.Qs);
    const uint32_t s_k0 = smem_u32(sm.Ks[0]);
    const uint32_t s_v0 = smem_u32(sm.Vs[0]);
    const uint32_t s_m0 = smem_u32(&sm.msk[0][0][0]);

    // ---- load Q block (64 rows x 64B) into smem ----
    {
        const char* src = (const char*)(g_Qb + (size_t)q0 * DD + h * HD);
#pragma unroll
        for (int j = 0; j < 2; j++) {
            int chunk = tid + j * 128;          // 256 chunks of 16B
            int r = chunk >> 2, c = chunk & 3;
            *(uint4*)((char*)sm.Qs + r * 80 + c * 16) =
                *(const uint4*)(src + (size_t)r * DD * 2 + c * 16);
        }
    }

    // ---- prologue: issue tile 0 ----
    const char* ksrc = (const char*)(g_Kb + h * HD);
    const char* vsrc = (const char*)(g_Vb + h * HD);
    {
#pragma unroll
        for (int j = 0; j < 4; j++) {
            int chunk = tid + j * 128;          // 512 chunks
            int r = chunk >> 2, c = chunk & 3;
            uint32_t off = (uint32_t)(r * 80 + c * 16);
            size_t gsrc = (size_t)r * DD * 2 + c * 16;
            cp16(s_k0 + off, ksrc + gsrc);
            cp16(s_v0 + off, vsrc + gsrc);
        }
        if (tid < 64)
            cp16(s_m0 + tid * 16, g_mask + (size_t)(q0 + tid) * NWORDS);
        CP_COMMIT();
    }

    __syncthreads();

    // ---- Q fragments (once) ----
    const int wq0 = wid * 16;
    const int g = lane >> 2, tig = lane & 3;
    uint32_t aq[2][4];
    {
        int m = lane >> 3, r = lane & 7;
        uint32_t base = s_q + (uint32_t)((wq0 + (m & 1) * 8 + r) * 80 + (m >> 1) * 16);
        ldsm_x4(aq[0], base);
        ldsm_x4(aq[1], base + 32);  // k 16..31
    }

    float o[4][4];
#pragma unroll
    for (int v = 0; v < 4; v++)
#pragma unroll
        for (int i = 0; i < 4; i++) o[v][i] = 0.f;
    float ls0 = 0.f, ls1 = 0.f;

    const uint32_t k_lane_off = (uint32_t)((lane & 7) * 80 + (lane >> 3) * 16);
    const uint32_t v_lane_off = (uint32_t)(((lane >> 3) & 1) * 8 * 80 + (lane & 7) * 80 +
                                           (lane >> 4) * 16);

    for (int t = 0; t < 32; t++) {
        int buf = t & 1;
        // issue next tile
        if (t < 31) {
            int nb = (t + 1) & 1;
            uint32_t skb = s_k0 + (uint32_t)nb * (128 * 80);
            uint32_t svb = s_v0 + (uint32_t)nb * (128 * 80);
            size_t tbase = (size_t)(t + 1) * 128 * DD * 2;
#pragma unroll
            for (int j = 0; j < 4; j++) {
                int chunk = tid + j * 128;
                int r = chunk >> 2, c = chunk & 3;
                uint32_t off = (uint32_t)(r * 80 + c * 16);
                size_t gsrc = tbase + (size_t)r * DD * 2 + c * 16;
                cp16(skb + off, ksrc + gsrc);
                cp16(svb + off, vsrc + gsrc);
            }
            if (tid < 64)
                cp16(s_m0 + (uint32_t)nb * 1024 + tid * 16,
                     g_mask + (size_t)(q0 + tid) * NWORDS + (t + 1) * 4);
            CP_COMMIT();
            CP_WAIT(1);
        } else {
            CP_WAIT(0);
        }
        __syncthreads();

        const uint32_t kb_base = s_k0 + (uint32_t)buf * (128 * 80);
        const uint32_t vb_base = s_v0 + (uint32_t)buf * (128 * 80);

        // ---- S = Q @ K^T  (16x128 per warp) ----
        float c[16][4];
#pragma unroll
        for (int nt = 0; nt < 16; nt++) {
            c[nt][0] = c[nt][1] = c[nt][2] = c[nt][3] = 0.f;
            uint32_t kb[4];
            ldsm_x4(kb, kb_base + (uint32_t)nt * (8 * 80) + k_lane_off);
            mma_bf16(c[nt], aq[0], kb);
            mma_bf16(c[nt], aq[1], kb + 2);
        }

        // ---- epilogue: P = mask ? exp2(S) : 0, pack to A fragments ----
        uint32_t mw0[4], mw1[4];
        {
            uint4 a = *(uint4*)&sm.msk[buf][wq0 + g][0];
            uint4 b = *(uint4*)&sm.msk[buf][wq0 + g + 8][0];
            mw0[0] = a.x; mw0[1] = a.y; mw0[2] = a.z; mw0[3] = a.w;
            mw1[0] = b.x; mw1[1] = b.y; mw1[2] = b.z; mw1[3] = b.w;
        }
        uint32_t ap[8][4];
#pragma unroll
        for (int nt = 0; nt < 16; nt++) {
            int sh = (nt & 3) * 8 + 2 * tig;
            uint32_t w0 = mw0[nt >> 2] >> sh;
            uint32_t w1 = mw1[nt >> 2] >> sh;
            float p0 = (w0 & 1u)        ? ex2f(c[nt][0]) : 0.f;
            float p1 = ((w0 >> 1) & 1u) ? ex2f(c[nt][1]) : 0.f;
            float p2 = (w1 & 1u)        ? ex2f(c[nt][2]) : 0.f;
            float p3 = ((w1 >> 1) & 1u) ? ex2f(c[nt][3]) : 0.f;
            ls0 += p0 + p1;
            ls1 += p2 + p3;
            ap[nt >> 1][(nt & 1) * 2 + 0] = pack_bf16x2(p0, p1);
            ap[nt >> 1][(nt & 1) * 2 + 1] = pack_bf16x2(p2, p3);
        }

        // ---- O += P @ V ----
#pragma unroll
        for (int kt = 0; kt < 8; kt++) {
            uint32_t vb[4];
            uint32_t base = vb_base + (uint32_t)kt * (16 * 80) + v_lane_off;
            ldsm_x4_t(vb, base);
            mma_bf16(o[0], ap[kt], vb);
            mma_bf16(o[1], ap[kt], vb + 2);
            ldsm_x4_t(vb, base + 32);   // d cols 16..31
            mma_bf16(o[2], ap[kt], vb);
            mma_bf16(o[3], ap[kt], vb + 2);
        }
        __syncthreads();
    }

    // ---- finalize: row-sum reduce, divide, store ----
    ls0 += __shfl_xor_sync(0xFFFFFFFF, ls0, 1);
    ls0 += __shfl_xor_sync(0xFFFFFFFF, ls0, 2);
    ls1 += __shfl_xor_sync(0xFFFFFFFF, ls1, 1);
    ls1 += __shfl_xor_sync(0xFFFFFFFF, ls1, 2);
    float inv0 = 1.f / ls0, inv1 = 1.f / ls1;

    int qrow = q0 + wq0 + g;
    float* dst0 = g_att + (size_t)qrow * DD + h * HD + 2 * tig;
    float* dst1 = dst0 + 8 * DD;
#pragma unroll
    for (int v = 0; v < 4; v++) {
        *(float2*)(dst0 + v * 8) = make_float2(o[v][0] * inv0, o[v][1] * inv0);
        *(float2*)(dst1 + v * 8) = make_float2(o[v][2] * inv1, o[v][3] * inv1);
    }
}

// ================= 6. residual + LayerNorm =================
__global__ void ln_kernel(const float* __restrict__ tmp,
                          const float* __restrict__ x,
                          const float* __restrict__ w,
                          const float* __restrict__ b,
                          float* __restrict__ out) {
    int n = blockIdx.x;
    int tid = threadIdx.x;  // 256 == DD
    float v = tmp[n * DD + tid] + x[n * DD + tid];
    __shared__ float s1[256], s2[256];
    s1[tid] = v;
    s2[tid] = v * v;
    __syncthreads();
    for (int st = 128; st > 0; st >>= 1) {
        if (tid < st) { s1[tid] += s1[tid + st]; s2[tid] += s2[tid + st]; }
        __syncthreads();
    }
    float mu = s1[0] * (1.f / 256.f);
    float var = s2[0] * (1.f / 256.f) - mu * mu;
    float inv = rsqrtf(var + 1e-5f);
    out[n * DD + tid] = (v - mu) * inv * w[tid] + b[tid];
}

// ================= launch =================
extern "C" void kernel_launch(void* const* d_in, const int* in_sizes, int n_in,
                              void* d_out, int out_size) {
    const float* x   = (const float*)d_in[0];
    const int*   ei  = (const int*)d_in[1];
    const float* Wq  = (const float*)d_in[2];
    const float* bq  = (const float*)d_in[3];
    const float* Wk  = (const float*)d_in[4];
    const float* bk  = (const float*)d_in[5];
    const float* Wv  = (const float*)d_in[6];
    const float* bv  = (const float*)d_in[7];
    const float* Wo  = (const float*)d_in[8];
    const float* bo  = (const float*)d_in[9];
    const float* lnw = (const float*)d_in[10];
    const float* lnb = (const float*)d_in[11];
    float* out = (float*)d_out;

    float *gA, *gT;
    cudaGetSymbolAddress((void**)&gA, g_att);
    cudaGetSymbolAddress((void**)&gT, g_tmp);

    // mask pipeline
    adj_init_kernel<<<(NN * NWORDS) / 256, 256>>>();
    edge_kernel<<<EE / 256, 256>>>(ei);
    mask_kernel<<<NN, NWORDS>>>();

    // QKV projections (bf16 out, Q pre-scaled)
    qkv_kernel<<<dim3(DD / GBN, NN / GBM, 3), 256>>>(x, Wq, bq, Wk, bk, Wv, bv);

    // tensor-core attention (mma.sync)
    attn_kernel<<<dim3(NN / 64, HH), 128>>>();

    // output projection + residual + LN
    gemm_bias_kernel<<<dim3(DD / GBN, NN / GBM), 256>>>(gA, Wo, bo, gT);
    ln_kernel<<<NN, 256>>>(gT, x, lnw, lnb, out);
}

// round 4
// speedup vs baseline: 10.7286x; 1.4194x over previous
#include <cuda_runtime.h>
#include <cuda_bf16.h>
#include <math.h>
#include <stdint.h>

// ---------------- problem constants ----------------
#define NN 4096
#define DD 256
#define HH 8
#define HD 32
#define EE 65536
#define NWORDS 128
// (1/sqrt(32)) * log2(e): folded into Q so softmax weight = exp2(S)
#define QSCALE 0.25503486f

// ---------------- scratch globals (no allocs allowed) ----------------
__device__ uint32_t g_adj[NN * NWORDS];
__device__ uint32_t g_mask[NN * NWORDS];
__device__ __nv_bfloat16 g_xb[NN * DD];
__device__ __nv_bfloat16 g_Wb[4 * DD * DD];   // Wq, Wk, Wv, Wo (bf16)
__device__ __nv_bfloat16 g_Qb[NN * DD];       // pre-scaled by QSCALE
__device__ __nv_bfloat16 g_Kb[NN * DD];
__device__ __nv_bfloat16 g_Vb[NN * DD];
__device__ __nv_bfloat16 g_attb[NN * DD];     // attention output (bf16)
__device__ float g_tmp[NN * DD];

// ---------------- PTX helpers ----------------
__device__ __forceinline__ uint32_t smem_u32(const void* p) {
    uint32_t a;
    asm("{ .reg .u64 t; cvta.to.shared.u64 t, %1; cvt.u32.u64 %0, t; }"
        : "=r"(a) : "l"(p));
    return a;
}
__device__ __forceinline__ float ex2f(float x) {
    float y; asm("ex2.approx.ftz.f32 %0, %1;" : "=f"(y) : "f"(x)); return y;
}
__device__ __forceinline__ uint32_t pack_bf16x2(float lo, float hi) {
    uint32_t r;
    asm("cvt.rn.bf16x2.f32 %0, %1, %2;" : "=r"(r) : "f"(hi), "f"(lo));
    return r;
}
__device__ __forceinline__ void ldsm_x4(uint32_t* r, uint32_t addr) {
    asm volatile("ldmatrix.sync.aligned.m8n8.x4.shared.b16 {%0,%1,%2,%3}, [%4];"
        : "=r"(r[0]), "=r"(r[1]), "=r"(r[2]), "=r"(r[3]) : "r"(addr));
}
__device__ __forceinline__ void ldsm_x4_t(uint32_t* r, uint32_t addr) {
    asm volatile("ldmatrix.sync.aligned.m8n8.x4.trans.shared.b16 {%0,%1,%2,%3}, [%4];"
        : "=r"(r[0]), "=r"(r[1]), "=r"(r[2]), "=r"(r[3]) : "r"(addr));
}
__device__ __forceinline__ void mma_bf16(float* c, const uint32_t* a, const uint32_t* b) {
    asm volatile(
        "mma.sync.aligned.m16n8k16.row.col.f32.bf16.bf16.f32 "
        "{%0,%1,%2,%3}, {%4,%5,%6,%7}, {%8,%9}, {%0,%1,%2,%3};"
        : "+f"(c[0]), "+f"(c[1]), "+f"(c[2]), "+f"(c[3])
        : "r"(a[0]), "r"(a[1]), "r"(a[2]), "r"(a[3]), "r"(b[0]), "r"(b[1]));
}
__device__ __forceinline__ void cp16(uint32_t dst, const void* src) {
    asm volatile("cp.async.cg.shared.global [%0], [%1], 16;" :: "r"(dst), "l"(src));
}
#define CP_COMMIT() asm volatile("cp.async.commit_group;" ::: "memory")
#define CP_WAIT(n)  asm volatile("cp.async.wait_group %0;" :: "n"(n) : "memory")

// ================= 0. bf16 casts =================
__global__ void xcast_kernel(const float* __restrict__ x) {
    int i = (blockIdx.x * 256 + threadIdx.x) * 4;
    float4 v = *(const float4*)(x + i);
    *(uint2*)(g_xb + i) = make_uint2(pack_bf16x2(v.x, v.y), pack_bf16x2(v.z, v.w));
}
__global__ void wcast_kernel(const float* __restrict__ Wq, const float* __restrict__ Wk,
                             const float* __restrict__ Wv, const float* __restrict__ Wo) {
    int w = blockIdx.y;
    const float* src = (w == 0) ? Wq : (w == 1) ? Wk : (w == 2) ? Wv : Wo;
    int i = (blockIdx.x * 256 + threadIdx.x) * 4;
    float4 v = *(const float4*)(src + i);
    *(uint2*)(g_Wb + w * (DD * DD) + i) =
        make_uint2(pack_bf16x2(v.x, v.y), pack_bf16x2(v.z, v.w));
}

// ================= 1. adjacency init (zero + self loops) =================
__global__ void adj_init_kernel() {
    int idx = blockIdx.x * blockDim.x + threadIdx.x;
    int n = idx >> 7, w = idx & 127;
    uint32_t v = 0;
    if (w == (n >> 5)) v = 1u << (n & 31);
    g_adj[idx] = v;
}

// ================= 2. scatter edges (undirected) =================
__global__ void edge_kernel(const int* __restrict__ ei) {
    int e = blockIdx.x * blockDim.x + threadIdx.x;
    if (e >= EE) return;
    int s = ei[e], d = ei[EE + e];
    atomicOr(&g_adj[s * NWORDS + (d >> 5)], 1u << (d & 31));
    atomicOr(&g_adj[d * NWORDS + (s >> 5)], 1u << (s & 31));
}

// ================= 3. reach-2 mask =================
__global__ void mask_kernel() {
    int n = blockIdx.x;
    int tid = threadIdx.x;  // 128
    __shared__ uint32_t row[NWORDS];
    row[tid] = g_adj[n * NWORDS + tid];
    __syncthreads();
    uint32_t acc = 0;
    for (int w = 0; w < NWORDS; w++) {
        uint32_t bits = row[w];
        while (bits) {
            int b = __ffs(bits) - 1;
            bits &= bits - 1;
            acc |= g_adj[((w << 5) + b) * NWORDS + tid];
        }
    }
    g_mask[n * NWORDS + tid] = acc;
}

// ================= 4. bf16 tensor-core GEMM =================
// C[M=4096, N=256] = A[4096,256]@W[256,256] + bias. CTA tile 64x128, BK=32.
// 128 threads / 4 warps; warp computes 16 rows x 128 cols.
// A smem rows 80B (64B data), B smem rows 272B (256B data): 16*odd strides
// -> ldmatrix row-slot conflict-free.
template <bool FP32OUT>
__device__ __forceinline__ void gemm_core(const __nv_bfloat16* __restrict__ A,
                                          const __nv_bfloat16* __restrict__ W,
                                          const float* __restrict__ bias,
                                          void* __restrict__ Cv, float scale) {
    __shared__ __nv_bfloat16 sA[2][64 * 40];
    __shared__ __nv_bfloat16 sB[2][32 * 136];

    const int tid = threadIdx.x;
    const int wid = tid >> 5;
    const int lane = tid & 31;
    const int m0 = blockIdx.y * 64;
    const int n0 = blockIdx.x * 128;

    const uint32_t aA = smem_u32(sA);
    const uint32_t aB = smem_u32(sB);
    const char* Abase = (const char*)A + (size_t)m0 * (DD * 2);
    const char* Bbase = (const char*)W + (size_t)n0 * 2;

    // ---- issue chunk 0 ----
    {
#pragma unroll
        for (int j = 0; j < 2; j++) {
            int t = tid + j * 128;
            int r = t >> 2, c = t & 3;
            cp16(aA + r * 80 + c * 16, Abase + (size_t)r * 512 + c * 16);
        }
#pragma unroll
        for (int j = 0; j < 4; j++) {
            int t = tid + j * 128;
            int r = t >> 4, c = t & 15;
            cp16(aB + r * 272 + c * 16, Bbase + (size_t)r * 512 + c * 16);
        }
        CP_COMMIT();
    }

    float acc[16][4];
#pragma unroll
    for (int j = 0; j < 16; j++)
        acc[j][0] = acc[j][1] = acc[j][2] = acc[j][3] = 0.f;

    const int m = lane >> 3, rr = lane & 7;
    const uint32_t a_off = (uint32_t)((wid * 16 + (m & 1) * 8 + rr) * 80 + (m >> 1) * 16);
    const uint32_t b_lane = (uint32_t)(((lane >> 3) & 1) * 8 * 272 + (lane & 7) * 272 +
                                       (lane >> 4) * 16);

    for (int t = 0; t < 8; t++) {
        if (t < 7) {
            int nb = (t + 1) & 1;
            uint32_t dA = aA + (uint32_t)nb * 5120;
            uint32_t dB = aB + (uint32_t)nb * 8704;
            const char* As = Abase + (size_t)(t + 1) * 64;           // +32 k * 2B
            const char* Bs = Bbase + (size_t)(t + 1) * 32 * 512;     // +32 k rows
#pragma unroll
            for (int j = 0; j < 2; j++) {
                int u = tid + j * 128;
                int r = u >> 2, c = u & 3;
                cp16(dA + r * 80 + c * 16, As + (size_t)r * 512 + c * 16);
            }
#pragma unroll
            for (int j = 0; j < 4; j++) {
                int u = tid + j * 128;
                int r = u >> 4, c = u & 15;
                cp16(dB + r * 272 + c * 16, Bs + (size_t)r * 512 + c * 16);
            }
            CP_COMMIT();
            CP_WAIT(1);
        } else {
            CP_WAIT(0);
        }
        __syncthreads();

        const uint32_t bufA = aA + (uint32_t)(t & 1) * 5120;
        const uint32_t bufB = aB + (uint32_t)(t & 1) * 8704;

        uint32_t aq[2][4];
        ldsm_x4(aq[0], bufA + a_off);
        ldsm_x4(aq[1], bufA + a_off + 32);

#pragma unroll
        for (int ks = 0; ks < 2; ks++) {
#pragma unroll
            for (int j = 0; j < 8; j++) {
                uint32_t vb[4];
                ldsm_x4_t(vb, bufB + (uint32_t)(ks * 16 * 272 + j * 32) + b_lane);
                mma_bf16(acc[2 * j],     aq[ks], vb);
                mma_bf16(acc[2 * j + 1], aq[ks], vb + 2);
            }
        }
        __syncthreads();
    }

    // ---- epilogue ----
    const int gg = lane >> 2, tig = lane & 3;
    const int r0 = m0 + wid * 16 + gg;
#pragma unroll
    for (int j = 0; j < 16; j++) {
        int col = n0 + j * 8 + 2 * tig;
        float2 b2 = __ldg((const float2*)(bias + col));
        if (FP32OUT) {
            float* Cf = (float*)Cv;
            *(float2*)(Cf + (size_t)r0 * DD + col) =
                make_float2(acc[j][0] + b2.x, acc[j][1] + b2.y);
            *(float2*)(Cf + (size_t)(r0 + 8) * DD + col) =
                make_float2(acc[j][2] + b2.x, acc[j][3] + b2.y);
        } else {
            __nv_bfloat16* Cb = (__nv_bfloat16*)Cv;
            *(uint32_t*)(Cb + (size_t)r0 * DD + col) =
                pack_bf16x2((acc[j][0] + b2.x) * scale, (acc[j][1] + b2.y) * scale);
            *(uint32_t*)(Cb + (size_t)(r0 + 8) * DD + col) =
                pack_bf16x2((acc[j][2] + b2.x) * scale, (acc[j][3] + b2.y) * scale);
        }
    }
}

__global__ void __launch_bounds__(128) qkv_gemm_kernel(const float* __restrict__ bq,
                                                       const float* __restrict__ bk,
                                                       const float* __restrict__ bv) {
    int z = blockIdx.z;
    const float* bias = (z == 0) ? bq : (z == 1) ? bk : bv;
    __nv_bfloat16* C = (z == 0) ? g_Qb : (z == 1) ? g_Kb : g_Vb;
    float scale = (z == 0) ? QSCALE : 1.f;
    gemm_core<false>(g_xb, g_Wb + (size_t)z * DD * DD, bias, C, scale);
}
__global__ void __launch_bounds__(128) wo_gemm_kernel(const float* __restrict__ bo) {
    gemm_core<true>(g_attb, g_Wb + (size_t)3 * DD * DD, bo, g_tmp, 1.f);
}

// ================= 5. mma.sync attention =================
// CTA: 128 threads (4 warps), 64 queries, one head. 32 kv tiles of 128 keys.
#define RS 40   // row stride in bf16 units (80 bytes)

struct AttnSmem {
    __nv_bfloat16 Qs[64 * RS];          // 5120 B
    __nv_bfloat16 Ks[2][128 * RS];      // 2 x 10240 B
    __nv_bfloat16 Vs[2][128 * RS];      // 2 x 10240 B
    uint32_t msk[2][64][4];             // 2 x 1024 B
};

__global__ void __launch_bounds__(128, 3) attn_kernel() {
    __shared__ AttnSmem sm;
    const int tid = threadIdx.x;
    const int wid = tid >> 5;
    const int lane = tid & 31;
    const int h = blockIdx.y;
    const int q0 = blockIdx.x * 64;

    const uint32_t s_q = smem_u32(sm.Qs);
    const uint32_t s_k0 = smem_u32(sm.Ks[0]);
    const uint32_t s_v0 = smem_u32(sm.Vs[0]);
    const uint32_t s_m0 = smem_u32(&sm.msk[0][0][0]);

    // ---- load Q block ----
    {
        const char* src = (const char*)(g_Qb + (size_t)q0 * DD + h * HD);
#pragma unroll
        for (int j = 0; j < 2; j++) {
            int chunk = tid + j * 128;
            int r = chunk >> 2, c = chunk & 3;
            *(uint4*)((char*)sm.Qs + r * 80 + c * 16) =
                *(const uint4*)(src + (size_t)r * DD * 2 + c * 16);
        }
    }

    const char* ksrc = (const char*)(g_Kb + h * HD);
    const char* vsrc = (const char*)(g_Vb + h * HD);
    {
#pragma unroll
        for (int j = 0; j < 4; j++) {
            int chunk = tid + j * 128;
            int r = chunk >> 2, c = chunk & 3;
            uint32_t off = (uint32_t)(r * 80 + c * 16);
            size_t gsrc = (size_t)r * DD * 2 + c * 16;
            cp16(s_k0 + off, ksrc + gsrc);
            cp16(s_v0 + off, vsrc + gsrc);
        }
        if (tid < 64)
            cp16(s_m0 + tid * 16, g_mask + (size_t)(q0 + tid) * NWORDS);
        CP_COMMIT();
    }

    __syncthreads();

    const int wq0 = wid * 16;
    const int g = lane >> 2, tig = lane & 3;
    uint32_t aq[2][4];
    {
        int m = lane >> 3, r = lane & 7;
        uint32_t base = s_q + (uint32_t)((wq0 + (m & 1) * 8 + r) * 80 + (m >> 1) * 16);
        ldsm_x4(aq[0], base);
        ldsm_x4(aq[1], base + 32);
    }

    float o[4][4];
#pragma unroll
    for (int v = 0; v < 4; v++)
#pragma unroll
        for (int i = 0; i < 4; i++) o[v][i] = 0.f;
    float ls0 = 0.f, ls1 = 0.f;

    const uint32_t k_lane_off = (uint32_t)((lane & 7) * 80 + (lane >> 3) * 16);
    const uint32_t v_lane_off = (uint32_t)(((lane >> 3) & 1) * 8 * 80 + (lane & 7) * 80 +
                                           (lane >> 4) * 16);

    for (int t = 0; t < 32; t++) {
        int buf = t & 1;
        if (t < 31) {
            int nb = (t + 1) & 1;
            uint32_t skb = s_k0 + (uint32_t)nb * (128 * 80);
            uint32_t svb = s_v0 + (uint32_t)nb * (128 * 80);
            size_t tbase = (size_t)(t + 1) * 128 * DD * 2;
#pragma unroll
            for (int j = 0; j < 4; j++) {
                int chunk = tid + j * 128;
                int r = chunk >> 2, c = chunk & 3;
                uint32_t off = (uint32_t)(r * 80 + c * 16);
                size_t gsrc = tbase + (size_t)r * DD * 2 + c * 16;
                cp16(skb + off, ksrc + gsrc);
                cp16(svb + off, vsrc + gsrc);
            }
            if (tid < 64)
                cp16(s_m0 + (uint32_t)nb * 1024 + tid * 16,
                     g_mask + (size_t)(q0 + tid) * NWORDS + (t + 1) * 4);
            CP_COMMIT();
            CP_WAIT(1);
        } else {
            CP_WAIT(0);
        }
        __syncthreads();

        const uint32_t kb_base = s_k0 + (uint32_t)buf * (128 * 80);
        const uint32_t vb_base = s_v0 + (uint32_t)buf * (128 * 80);

        float c[16][4];
#pragma unroll
        for (int nt = 0; nt < 16; nt++) {
            c[nt][0] = c[nt][1] = c[nt][2] = c[nt][3] = 0.f;
            uint32_t kb[4];
            ldsm_x4(kb, kb_base + (uint32_t)nt * (8 * 80) + k_lane_off);
            mma_bf16(c[nt], aq[0], kb);
            mma_bf16(c[nt], aq[1], kb + 2);
        }

        uint32_t mw0[4], mw1[4];
        {
            uint4 a = *(uint4*)&sm.msk[buf][wq0 + g][0];
            uint4 b = *(uint4*)&sm.msk[buf][wq0 + g + 8][0];
            mw0[0] = a.x; mw0[1] = a.y; mw0[2] = a.z; mw0[3] = a.w;
            mw1[0] = b.x; mw1[1] = b.y; mw1[2] = b.z; mw1[3] = b.w;
        }
        uint32_t ap[8][4];
#pragma unroll
        for (int nt = 0; nt < 16; nt++) {
            int sh = (nt & 3) * 8 + 2 * tig;
            uint32_t w0 = mw0[nt >> 2] >> sh;
            uint32_t w1 = mw1[nt >> 2] >> sh;
            float p0 = (w0 & 1u)        ? ex2f(c[nt][0]) : 0.f;
            float p1 = ((w0 >> 1) & 1u) ? ex2f(c[nt][1]) : 0.f;
            float p2 = (w1 & 1u)        ? ex2f(c[nt][2]) : 0.f;
            float p3 = ((w1 >> 1) & 1u) ? ex2f(c[nt][3]) : 0.f;
            ls0 += p0 + p1;
            ls1 += p2 + p3;
            ap[nt >> 1][(nt & 1) * 2 + 0] = pack_bf16x2(p0, p1);
            ap[nt >> 1][(nt & 1) * 2 + 1] = pack_bf16x2(p2, p3);
        }

#pragma unroll
        for (int kt = 0; kt < 8; kt++) {
            uint32_t vb[4];
            uint32_t base = vb_base + (uint32_t)kt * (16 * 80) + v_lane_off;
            ldsm_x4_t(vb, base);
            mma_bf16(o[0], ap[kt], vb);
            mma_bf16(o[1], ap[kt], vb + 2);
            ldsm_x4_t(vb, base + 32);
            mma_bf16(o[2], ap[kt], vb);
            mma_bf16(o[3], ap[kt], vb + 2);
        }
        __syncthreads();
    }

    ls0 += __shfl_xor_sync(0xFFFFFFFF, ls0, 1);
    ls0 += __shfl_xor_sync(0xFFFFFFFF, ls0, 2);
    ls1 += __shfl_xor_sync(0xFFFFFFFF, ls1, 1);
    ls1 += __shfl_xor_sync(0xFFFFFFFF, ls1, 2);
    float inv0 = 1.f / ls0, inv1 = 1.f / ls1;

    int qrow = q0 + wq0 + g;
    __nv_bfloat16* dst0 = g_attb + (size_t)qrow * DD + h * HD + 2 * tig;
    __nv_bfloat16* dst1 = dst0 + 8 * DD;
#pragma unroll
    for (int v = 0; v < 4; v++) {
        *(uint32_t*)(dst0 + v * 8) = pack_bf16x2(o[v][0] * inv0, o[v][1] * inv0);
        *(uint32_t*)(dst1 + v * 8) = pack_bf16x2(o[v][2] * inv1, o[v][3] * inv1);
    }
}

// ================= 6. residual + LayerNorm =================
__global__ void ln_kernel(const float* __restrict__ tmp,
                          const float* __restrict__ x,
                          const float* __restrict__ w,
                          const float* __restrict__ b,
                          float* __restrict__ out) {
    int n = blockIdx.x;
    int tid = threadIdx.x;  // 256 == DD
    float v = tmp[n * DD + tid] + x[n * DD + tid];
    __shared__ float s1[256], s2[256];
    s1[tid] = v;
    s2[tid] = v * v;
    __syncthreads();
    for (int st = 128; st > 0; st >>= 1) {
        if (tid < st) { s1[tid] += s1[tid + st]; s2[tid] += s2[tid + st]; }
        __syncthreads();
    }
    float mu = s1[0] * (1.f / 256.f);
    float var = s2[0] * (1.f / 256.f) - mu * mu;
    float inv = rsqrtf(var + 1e-5f);
    out[n * DD + tid] = (v - mu) * inv * w[tid] + b[tid];
}

// ================= launch =================
extern "C" void kernel_launch(void* const* d_in, const int* in_sizes, int n_in,
                              void* d_out, int out_size) {
    const float* x   = (const float*)d_in[0];
    const int*   ei  = (const int*)d_in[1];
    const float* Wq  = (const float*)d_in[2];
    const float* bq  = (const float*)d_in[3];
    const float* Wk  = (const float*)d_in[4];
    const float* bk  = (const float*)d_in[5];
    const float* Wv  = (const float*)d_in[6];
    const float* bv  = (const float*)d_in[7];
    const float* Wo  = (const float*)d_in[8];
    const float* bo  = (const float*)d_in[9];
    const float* lnw = (const float*)d_in[10];
    const float* lnb = (const float*)d_in[11];
    float* out = (float*)d_out;

    float* gT;
    cudaGetSymbolAddress((void**)&gT, g_tmp);

    // casts + mask pipeline
    xcast_kernel<<<NN * DD / 1024, 256>>>(x);
    wcast_kernel<<<dim3(DD * DD / 1024, 4), 256>>>(Wq, Wk, Wv, Wo);
    adj_init_kernel<<<(NN * NWORDS) / 256, 256>>>();
    edge_kernel<<<EE / 256, 256>>>(ei);
    mask_kernel<<<NN, NWORDS>>>();

    // QKV projections (tensor core, bf16 out, Q pre-scaled)
    qkv_gemm_kernel<<<dim3(DD / 128, NN / 64, 3), 128>>>(bq, bk, bv);

    // tensor-core attention
    attn_kernel<<<dim3(NN / 64, HH), 128>>>();

    // output projection (tensor core, fp32 out) + residual + LN
    wo_gemm_kernel<<<dim3(DD / 128, NN / 64), 128>>>(bo);
    ln_kernel<<<NN, 256>>>(gT, x, lnw, lnb, out);
}

// round 5
// speedup vs baseline: 10.9368x; 1.0194x over previous
#include <cuda_runtime.h>
#include <cuda_bf16.h>
#include <math.h>
#include <stdint.h>

// ---------------- problem constants ----------------
#define NN 4096
#define DD 256
#define HH 8
#define HD 32
#define EE 65536
#define NWORDS 128
// (1/sqrt(32)) * log2(e): folded into Q so softmax weight = exp2(S)
#define QSCALE 0.25503486f

// ---------------- scratch globals (no allocs allowed) ----------------
__device__ uint32_t g_adj[NN * NWORDS];
__device__ uint32_t g_mask[NN * NWORDS];
__device__ __nv_bfloat16 g_xb[NN * DD];
__device__ __nv_bfloat16 g_Wb[4 * DD * DD];   // Wq, Wk, Wv, Wo (bf16)
__device__ __nv_bfloat16 g_Qb[NN * DD];       // pre-scaled by QSCALE
__device__ __nv_bfloat16 g_Kb[NN * DD];
__device__ __nv_bfloat16 g_Vb[NN * DD];
__device__ __nv_bfloat16 g_attb[NN * DD];     // attention output (bf16)
__device__ float g_tmp[NN * DD];

// ---------------- PTX helpers ----------------
__device__ __forceinline__ uint32_t smem_u32(const void* p) {
    uint32_t a;
    asm("{ .reg .u64 t; cvta.to.shared.u64 t, %1; cvt.u32.u64 %0, t; }"
        : "=r"(a) : "l"(p));
    return a;
}
__device__ __forceinline__ uint32_t pack_bf16x2(float lo, float hi) {
    uint32_t r;
    asm("cvt.rn.bf16x2.f32 %0, %1, %2;" : "=r"(r) : "f"(hi), "f"(lo));
    return r;
}
__device__ __forceinline__ uint32_t ex2_bf16x2(uint32_t x) {
    uint32_t y;
    asm("ex2.approx.ftz.bf16x2 %0, %1;" : "=r"(y) : "r"(x));
    return y;
}
__device__ __forceinline__ void ldsm_x4(uint32_t* r, uint32_t addr) {
    asm volatile("ldmatrix.sync.aligned.m8n8.x4.shared.b16 {%0,%1,%2,%3}, [%4];"
        : "=r"(r[0]), "=r"(r[1]), "=r"(r[2]), "=r"(r[3]) : "r"(addr));
}
__device__ __forceinline__ void ldsm_x4_t(uint32_t* r, uint32_t addr) {
    asm volatile("ldmatrix.sync.aligned.m8n8.x4.trans.shared.b16 {%0,%1,%2,%3}, [%4];"
        : "=r"(r[0]), "=r"(r[1]), "=r"(r[2]), "=r"(r[3]) : "r"(addr));
}
__device__ __forceinline__ void mma_bf16(float* c, const uint32_t* a, const uint32_t* b) {
    asm volatile(
        "mma.sync.aligned.m16n8k16.row.col.f32.bf16.bf16.f32 "
        "{%0,%1,%2,%3}, {%4,%5,%6,%7}, {%8,%9}, {%0,%1,%2,%3};"
        : "+f"(c[0]), "+f"(c[1]), "+f"(c[2]), "+f"(c[3])
        : "r"(a[0]), "r"(a[1]), "r"(a[2]), "r"(a[3]), "r"(b[0]), "r"(b[1]));
}
__device__ __forceinline__ void cp16(uint32_t dst, const void* src) {
    asm volatile("cp.async.cg.shared.global [%0], [%1], 16;" :: "r"(dst), "l"(src));
}
#define CP_COMMIT() asm volatile("cp.async.commit_group;" ::: "memory")
#define CP_WAIT(n)  asm volatile("cp.async.wait_group %0;" :: "n"(n) : "memory")

// ================= 0. bf16 casts =================
__global__ void xcast_kernel(const float* __restrict__ x) {
    int i = (blockIdx.x * 256 + threadIdx.x) * 4;
    float4 v = *(const float4*)(x + i);
    *(uint2*)(g_xb + i) = make_uint2(pack_bf16x2(v.x, v.y), pack_bf16x2(v.z, v.w));
}
__global__ void wcast_kernel(const float* __restrict__ Wq, const float* __restrict__ Wk,
                             const float* __restrict__ Wv, const float* __restrict__ Wo) {
    int w = blockIdx.y;
    const float* src = (w == 0) ? Wq : (w == 1) ? Wk : (w == 2) ? Wv : Wo;
    int i = (blockIdx.x * 256 + threadIdx.x) * 4;
    float4 v = *(const float4*)(src + i);
    *(uint2*)(g_Wb + w * (DD * DD) + i) =
        make_uint2(pack_bf16x2(v.x, v.y), pack_bf16x2(v.z, v.w));
}

// ================= 1. adjacency init (zero + self loops) =================
__global__ void adj_init_kernel() {
    int idx = blockIdx.x * blockDim.x + threadIdx.x;
    int n = idx >> 7, w = idx & 127;
    uint32_t v = 0;
    if (w == (n >> 5)) v = 1u << (n & 31);
    g_adj[idx] = v;
}

// ================= 2. scatter edges (undirected) =================
__global__ void edge_kernel(const int* __restrict__ ei) {
    int e = blockIdx.x * blockDim.x + threadIdx.x;
    if (e >= EE) return;
    int s = ei[e], d = ei[EE + e];
    atomicOr(&g_adj[s * NWORDS + (d >> 5)], 1u << (d & 31));
    atomicOr(&g_adj[d * NWORDS + (s >> 5)], 1u << (s & 31));
}

// ================= 3. reach-2 mask =================
__global__ void mask_kernel() {
    int n = blockIdx.x;
    int tid = threadIdx.x;  // 128
    __shared__ uint32_t row[NWORDS];
    row[tid] = g_adj[n * NWORDS + tid];
    __syncthreads();
    uint32_t acc = 0;
    for (int w = 0; w < NWORDS; w++) {
        uint32_t bits = row[w];
        while (bits) {
            int b = __ffs(bits) - 1;
            bits &= bits - 1;
            acc |= g_adj[((w << 5) + b) * NWORDS + tid];
        }
    }
    g_mask[n * NWORDS + tid] = acc;
}

// ================= 4. bf16 tensor-core GEMM =================
// C[M=4096, N=256] = A[4096,256]@W[256,256] + bias. CTA tile 64x128, BK=32.
template <bool FP32OUT>
__device__ __forceinline__ void gemm_core(const __nv_bfloat16* __restrict__ A,
                                          const __nv_bfloat16* __restrict__ W,
                                          const float* __restrict__ bias,
                                          void* __restrict__ Cv, float scale) {
    __shared__ __nv_bfloat16 sA[2][64 * 40];
    __shared__ __nv_bfloat16 sB[2][32 * 136];

    const int tid = threadIdx.x;
    const int wid = tid >> 5;
    const int lane = tid & 31;
    const int m0 = blockIdx.y * 64;
    const int n0 = blockIdx.x * 128;

    const uint32_t aA = smem_u32(sA);
    const uint32_t aB = smem_u32(sB);
    const char* Abase = (const char*)A + (size_t)m0 * (DD * 2);
    const char* Bbase = (const char*)W + (size_t)n0 * 2;

    {
#pragma unroll
        for (int j = 0; j < 2; j++) {
            int t = tid + j * 128;
            int r = t >> 2, c = t & 3;
            cp16(aA + r * 80 + c * 16, Abase + (size_t)r * 512 + c * 16);
        }
#pragma unroll
        for (int j = 0; j < 4; j++) {
            int t = tid + j * 128;
            int r = t >> 4, c = t & 15;
            cp16(aB + r * 272 + c * 16, Bbase + (size_t)r * 512 + c * 16);
        }
        CP_COMMIT();
    }

    float acc[16][4];
#pragma unroll
    for (int j = 0; j < 16; j++)
        acc[j][0] = acc[j][1] = acc[j][2] = acc[j][3] = 0.f;

    const int m = lane >> 3, rr = lane & 7;
    const uint32_t a_off = (uint32_t)((wid * 16 + (m & 1) * 8 + rr) * 80 + (m >> 1) * 16);
    const uint32_t b_lane = (uint32_t)(((lane >> 3) & 1) * 8 * 272 + (lane & 7) * 272 +
                                       (lane >> 4) * 16);

    for (int t = 0; t < 8; t++) {
        if (t < 7) {
            int nb = (t + 1) & 1;
            uint32_t dA = aA + (uint32_t)nb * 5120;
            uint32_t dB = aB + (uint32_t)nb * 8704;
            const char* As = Abase + (size_t)(t + 1) * 64;
            const char* Bs = Bbase + (size_t)(t + 1) * 32 * 512;
#pragma unroll
            for (int j = 0; j < 2; j++) {
                int u = tid + j * 128;
                int r = u >> 2, c = u & 3;
                cp16(dA + r * 80 + c * 16, As + (size_t)r * 512 + c * 16);
            }
#pragma unroll
            for (int j = 0; j < 4; j++) {
                int u = tid + j * 128;
                int r = u >> 4, c = u & 15;
                cp16(dB + r * 272 + c * 16, Bs + (size_t)r * 512 + c * 16);
            }
            CP_COMMIT();
            CP_WAIT(1);
        } else {
            CP_WAIT(0);
        }
        __syncthreads();

        const uint32_t bufA = aA + (uint32_t)(t & 1) * 5120;
        const uint32_t bufB = aB + (uint32_t)(t & 1) * 8704;

        uint32_t aq[2][4];
        ldsm_x4(aq[0], bufA + a_off);
        ldsm_x4(aq[1], bufA + a_off + 32);

#pragma unroll
        for (int ks = 0; ks < 2; ks++) {
#pragma unroll
            for (int j = 0; j < 8; j++) {
                uint32_t vb[4];
                ldsm_x4_t(vb, bufB + (uint32_t)(ks * 16 * 272 + j * 32) + b_lane);
                mma_bf16(acc[2 * j],     aq[ks], vb);
                mma_bf16(acc[2 * j + 1], aq[ks], vb + 2);
            }
        }
        __syncthreads();
    }

    const int gg = lane >> 2, tig = lane & 3;
    const int r0 = m0 + wid * 16 + gg;
#pragma unroll
    for (int j = 0; j < 16; j++) {
        int col = n0 + j * 8 + 2 * tig;
        float2 b2 = __ldg((const float2*)(bias + col));
        if (FP32OUT) {
            float* Cf = (float*)Cv;
            *(float2*)(Cf + (size_t)r0 * DD + col) =
                make_float2(acc[j][0] + b2.x, acc[j][1] + b2.y);
            *(float2*)(Cf + (size_t)(r0 + 8) * DD + col) =
                make_float2(acc[j][2] + b2.x, acc[j][3] + b2.y);
        } else {
            __nv_bfloat16* Cb = (__nv_bfloat16*)Cv;
            *(uint32_t*)(Cb + (size_t)r0 * DD + col) =
                pack_bf16x2((acc[j][0] + b2.x) * scale, (acc[j][1] + b2.y) * scale);
            *(uint32_t*)(Cb + (size_t)(r0 + 8) * DD + col) =
                pack_bf16x2((acc[j][2] + b2.x) * scale, (acc[j][3] + b2.y) * scale);
        }
    }
}

__global__ void __launch_bounds__(128) qkv_gemm_kernel(const float* __restrict__ bq,
                                                       const float* __restrict__ bk,
                                                       const float* __restrict__ bv) {
    int z = blockIdx.z;
    const float* bias = (z == 0) ? bq : (z == 1) ? bk : bv;
    __nv_bfloat16* C = (z == 0) ? g_Qb : (z == 1) ? g_Kb : g_Vb;
    float scale = (z == 0) ? QSCALE : 1.f;
    gemm_core<false>(g_xb, g_Wb + (size_t)z * DD * DD, bias, C, scale);
}
__global__ void __launch_bounds__(128) wo_gemm_kernel(const float* __restrict__ bo) {
    gemm_core<true>(g_attb, g_Wb + (size_t)3 * DD * DD, bo, g_tmp, 1.f);
}

// ================= 5. mma.sync attention =================
// CTA: 256 threads (8 warps), 128 queries, one head. 32 kv tiles of 128 keys.
// K/V smem rows padded to 80B (conflict-free ldmatrix); Q rows 64B (one-time ldsm).
// Softmax weights via packed bf16x2 ex2; row-sum via ones-column MMA.
struct AttnSmem2 {
    __nv_bfloat16 Qs[128 * 32];       // 8192 B (64B rows)
    __nv_bfloat16 Ks[2][128 * 40];    // 2 x 10240 B
    __nv_bfloat16 Vs[2][128 * 40];    // 2 x 10240 B
};                                    // total 49152 B

__global__ void __launch_bounds__(256, 2) attn_kernel() {
    __shared__ AttnSmem2 sm;
    const int tid = threadIdx.x;
    const int wid = tid >> 5;        // 0..7
    const int lane = tid & 31;
    const int h = blockIdx.y;
    const int q0 = blockIdx.x * 128;

    const uint32_t s_q = smem_u32(sm.Qs);
    const uint32_t s_k0 = smem_u32(sm.Ks[0]);
    const uint32_t s_v0 = smem_u32(sm.Vs[0]);

    const char* ksrc = (const char*)(g_Kb + h * HD);
    const char* vsrc = (const char*)(g_Vb + h * HD);

    // ---- prologue: Q + K0/V0 via cp.async ----
    {
        const char* qsrc = (const char*)(g_Qb + (size_t)q0 * DD + h * HD);
#pragma unroll
        for (int j = 0; j < 2; j++) {
            int chunk = tid + j * 256;                 // 512 chunks
            int r = chunk >> 2, c = chunk & 3;
            cp16(s_q + (uint32_t)(r * 64 + c * 16), qsrc + (size_t)r * 512 + c * 16);
        }
#pragma unroll
        for (int j = 0; j < 2; j++) {
            int chunk = tid + j * 256;
            int r = chunk >> 2, c = chunk & 3;
            uint32_t off = (uint32_t)(r * 80 + c * 16);
            size_t gs = (size_t)r * 512 + c * 16;
            cp16(s_k0 + off, ksrc + gs);
            cp16(s_v0 + off, vsrc + gs);
        }
        CP_COMMIT();
    }

    const int wq0 = wid * 16;
    const int g = lane >> 2, tig = lane & 3;
    const int row0 = q0 + wq0 + g;

    // mask tile 0 (per-lane registers; broadcast within 4-lane quads via L1)
    uint4 mw_lo = *(const uint4*)(g_mask + (size_t)row0 * NWORDS);
    uint4 mw_hi = *(const uint4*)(g_mask + (size_t)(row0 + 8) * NWORDS);

    CP_WAIT(0);
    __syncthreads();

    // ---- Q fragments (once; 64B rows, one-time bank conflicts OK) ----
    uint32_t aq[2][4];
    {
        int m = lane >> 3, rr = lane & 7;
        uint32_t base = s_q + (uint32_t)((wq0 + (m & 1) * 8 + rr) * 64 + (m >> 1) * 16);
        ldsm_x4(aq[0], base);
        ldsm_x4(aq[1], base + 32);
    }

    float o[4][4];
#pragma unroll
    for (int v = 0; v < 4; v++)
#pragma unroll
        for (int i = 0; i < 4; i++) o[v][i] = 0.f;
    float lf[4] = {0.f, 0.f, 0.f, 0.f};
    uint32_t onesfrag[2];
    onesfrag[0] = onesfrag[1] = (lane < 4) ? 0x3F803F80u : 0u;

    const uint32_t k_lane_off = (uint32_t)((lane & 7) * 80 + (lane >> 3) * 16);
    const uint32_t v_lane_off = (uint32_t)(((lane >> 3) & 1) * 8 * 80 + (lane & 7) * 80 +
                                           (lane >> 4) * 16);

    for (int t = 0; t < 32; t++) {
        int buf = t & 1;
        uint4 mw_lo_n, mw_hi_n;
        if (t < 31) {
            // prefetch next mask words + next K/V tile
            mw_lo_n = *(const uint4*)(g_mask + (size_t)row0 * NWORDS + (t + 1) * 4);
            mw_hi_n = *(const uint4*)(g_mask + (size_t)(row0 + 8) * NWORDS + (t + 1) * 4);
            int nb = (t + 1) & 1;
            uint32_t skb = s_k0 + (uint32_t)nb * 10240;
            uint32_t svb = s_v0 + (uint32_t)nb * 10240;
            size_t tb = (size_t)(t + 1) * 128 * 512;
#pragma unroll
            for (int j = 0; j < 2; j++) {
                int chunk = tid + j * 256;
                int r = chunk >> 2, c = chunk & 3;
                uint32_t off = (uint32_t)(r * 80 + c * 16);
                size_t gs = tb + (size_t)r * 512 + c * 16;
                cp16(skb + off, ksrc + gs);
                cp16(svb + off, vsrc + gs);
            }
            CP_COMMIT();
            CP_WAIT(1);
        } else {
            CP_WAIT(0);
        }
        __syncthreads();

        const uint32_t kb_base = s_k0 + (uint32_t)buf * 10240;
        const uint32_t vb_base = s_v0 + (uint32_t)buf * 10240;
        const uint32_t mwl[4] = {mw_lo.x, mw_lo.y, mw_lo.z, mw_lo.w};
        const uint32_t mwh[4] = {mw_hi.x, mw_hi.y, mw_hi.z, mw_hi.w};

        uint32_t ap[8][4];
        // ---- S = Q@K^T in 4 column-quads; epilogue packs P in-register ----
#pragma unroll
        for (int qd = 0; qd < 4; qd++) {
            uint32_t kb[4][4];
#pragma unroll
            for (int nt = 0; nt < 4; nt++)
                ldsm_x4(kb[nt], kb_base + (uint32_t)((qd * 4 + nt) * (8 * 80)) + k_lane_off);
            float c4[4][4];
#pragma unroll
            for (int nt = 0; nt < 4; nt++) {
                c4[nt][0] = c4[nt][1] = c4[nt][2] = c4[nt][3] = 0.f;
                mma_bf16(c4[nt], aq[0], kb[nt]);
                mma_bf16(c4[nt], aq[1], kb[nt] + 2);
            }
            uint32_t w0 = mwl[qd] >> (2 * tig);
            uint32_t w1 = mwh[qd] >> (2 * tig);
#pragma unroll
            for (int nt = 0; nt < 4; nt++) {
                uint32_t b0 = w0 >> (nt * 8), b1 = w1 >> (nt * 8);
                uint32_t m01 = ((b0 & 1u) ? 0x0000FFFFu : 0u) | ((b0 & 2u) ? 0xFFFF0000u : 0u);
                uint32_t m23 = ((b1 & 1u) ? 0x0000FFFFu : 0u) | ((b1 & 2u) ? 0xFFFF0000u : 0u);
                uint32_t p01 = ex2_bf16x2(pack_bf16x2(c4[nt][0], c4[nt][1])) & m01;
                uint32_t p23 = ex2_bf16x2(pack_bf16x2(c4[nt][2], c4[nt][3])) & m23;
                int nth = qd * 4 + nt;
                ap[nth >> 1][(nth & 1) * 2 + 0] = p01;
                ap[nth >> 1][(nth & 1) * 2 + 1] = p23;
            }
        }

        // ---- O += P @ V ; lsum += P @ 1 (ones column on tensor core) ----
#pragma unroll
        for (int kt = 0; kt < 8; kt++) {
            uint32_t vb[4];
            uint32_t base = vb_base + (uint32_t)kt * (16 * 80) + v_lane_off;
            ldsm_x4_t(vb, base);
            mma_bf16(o[0], ap[kt], vb);
            mma_bf16(o[1], ap[kt], vb + 2);
            ldsm_x4_t(vb, base + 32);
            mma_bf16(o[2], ap[kt], vb);
            mma_bf16(o[3], ap[kt], vb + 2);
            mma_bf16(lf, ap[kt], onesfrag);
        }

        if (t < 31) { mw_lo = mw_lo_n; mw_hi = mw_hi_n; }
        __syncthreads();
    }

    // row sums live in col 0 of lf (lanes with tig==0): broadcast within quads
    float sum0 = __shfl_sync(0xFFFFFFFFu, lf[0], lane & 28);
    float sum1 = __shfl_sync(0xFFFFFFFFu, lf[2], lane & 28);
    float inv0 = 1.f / sum0, inv1 = 1.f / sum1;

    __nv_bfloat16* dst0 = g_attb + (size_t)row0 * DD + h * HD + 2 * tig;
    __nv_bfloat16* dst1 = dst0 + 8 * DD;
#pragma unroll
    for (int v = 0; v < 4; v++) {
        *(uint32_t*)(dst0 + v * 8) = pack_bf16x2(o[v][0] * inv0, o[v][1] * inv0);
        *(uint32_t*)(dst1 + v * 8) = pack_bf16x2(o[v][2] * inv1, o[v][3] * inv1);
    }
}

// ================= 6. residual + LayerNorm =================
__global__ void ln_kernel(const float* __restrict__ tmp,
                          const float* __restrict__ x,
                          const float* __restrict__ w,
                          const float* __restrict__ b,
                          float* __restrict__ out) {
    int n = blockIdx.x;
    int tid = threadIdx.x;  // 256 == DD
    float v = tmp[n * DD + tid] + x[n * DD + tid];
    __shared__ float s1[256], s2[256];
    s1[tid] = v;
    s2[tid] = v * v;
    __syncthreads();
    for (int st = 128; st > 0; st >>= 1) {
        if (tid < st) { s1[tid] += s1[tid + st]; s2[tid] += s2[tid + st]; }
        __syncthreads();
    }
    float mu = s1[0] * (1.f / 256.f);
    float var = s2[0] * (1.f / 256.f) - mu * mu;
    float inv = rsqrtf(var + 1e-5f);
    out[n * DD + tid] = (v - mu) * inv * w[tid] + b[tid];
}

// ================= launch =================
extern "C" void kernel_launch(void* const* d_in, const int* in_sizes, int n_in,
                              void* d_out, int out_size) {
    const float* x   = (const float*)d_in[0];
    const int*   ei  = (const int*)d_in[1];
    const float* Wq  = (const float*)d_in[2];
    const float* bq  = (const float*)d_in[3];
    const float* Wk  = (const float*)d_in[4];
    const float* bk  = (const float*)d_in[5];
    const float* Wv  = (const float*)d_in[6];
    const float* bv  = (const float*)d_in[7];
    const float* Wo  = (const float*)d_in[8];
    const float* bo  = (const float*)d_in[9];
    const float* lnw = (const float*)d_in[10];
    const float* lnb = (const float*)d_in[11];
    float* out = (float*)d_out;

    float* gT;
    cudaGetSymbolAddress((void**)&gT, g_tmp);

    // casts + mask pipeline
    xcast_kernel<<<NN * DD / 1024, 256>>>(x);
    wcast_kernel<<<dim3(DD * DD / 1024, 4), 256>>>(Wq, Wk, Wv, Wo);
    adj_init_kernel<<<(NN * NWORDS) / 256, 256>>>();
    edge_kernel<<<EE / 256, 256>>>(ei);
    mask_kernel<<<NN, NWORDS>>>();

    // QKV projections (tensor core, bf16 out, Q pre-scaled)
    qkv_gemm_kernel<<<dim3(DD / 128, NN / 64, 3), 128>>>(bq, bk, bv);

    // tensor-core attention
    attn_kernel<<<dim3(NN / 128, HH), 256>>>();

    // output projection (tensor core, fp32 out) + residual + LN
    wo_gemm_kernel<<<dim3(DD / 128, NN / 64), 128>>>(bo);
    ln_kernel<<<NN, 256>>>(gT, x, lnw, lnb, out);
}

// round 6
// speedup vs baseline: 13.0021x; 1.1888x over previous
#include <cuda_runtime.h>
#include <cuda_bf16.h>
#include <math.h>
#include <stdint.h>

// ---------------- problem constants ----------------
#define NN 4096
#define DD 256
#define HH 8
#define HD 32
#define EE 65536
#define NWORDS 128
// (1/sqrt(32)) * log2(e): folded into Q so softmax weight = exp2(S)
#define QSCALE 0.25503486f

// ---------------- scratch globals (no allocs allowed) ----------------
__device__ uint32_t g_adj[NN * NWORDS];
__device__ uint32_t g_mask[NN * NWORDS];
__device__ __nv_bfloat16 g_xb[NN * DD];
__device__ __nv_bfloat16 g_Wb[4 * DD * DD];   // Wq, Wk, Wv, Wo (bf16)
__device__ __nv_bfloat16 g_Qb[NN * DD];       // pre-scaled by QSCALE
__device__ __nv_bfloat16 g_Kb[NN * DD];
__device__ __nv_bfloat16 g_Vb[NN * DD];
__device__ __nv_bfloat16 g_attb[NN * DD];     // attention output (bf16)
__device__ float g_tmp[NN * DD];

// ---------------- PTX helpers ----------------
__device__ __forceinline__ uint32_t smem_u32(const void* p) {
    uint32_t a;
    asm("{ .reg .u64 t; cvta.to.shared.u64 t, %1; cvt.u32.u64 %0, t; }"
        : "=r"(a) : "l"(p));
    return a;
}
__device__ __forceinline__ uint32_t pack_bf16x2(float lo, float hi) {
    uint32_t r;
    asm("cvt.rn.bf16x2.f32 %0, %1, %2;" : "=r"(r) : "f"(hi), "f"(lo));
    return r;
}
__device__ __forceinline__ uint32_t ex2_bf16x2(uint32_t x) {
    uint32_t y;
    asm("ex2.approx.ftz.bf16x2 %0, %1;" : "=r"(y) : "r"(x));
    return y;
}
__device__ __forceinline__ void ldsm_x4(uint32_t* r, uint32_t addr) {
    asm volatile("ldmatrix.sync.aligned.m8n8.x4.shared.b16 {%0,%1,%2,%3}, [%4];"
        : "=r"(r[0]), "=r"(r[1]), "=r"(r[2]), "=r"(r[3]) : "r"(addr));
}
__device__ __forceinline__ void ldsm_x4_t(uint32_t* r, uint32_t addr) {
    asm volatile("ldmatrix.sync.aligned.m8n8.x4.trans.shared.b16 {%0,%1,%2,%3}, [%4];"
        : "=r"(r[0]), "=r"(r[1]), "=r"(r[2]), "=r"(r[3]) : "r"(addr));
}
__device__ __forceinline__ void mma_bf16(float* c, const uint32_t* a, const uint32_t* b) {
    asm volatile(
        "mma.sync.aligned.m16n8k16.row.col.f32.bf16.bf16.f32 "
        "{%0,%1,%2,%3}, {%4,%5,%6,%7}, {%8,%9}, {%0,%1,%2,%3};"
        : "+f"(c[0]), "+f"(c[1]), "+f"(c[2]), "+f"(c[3])
        : "r"(a[0]), "r"(a[1]), "r"(a[2]), "r"(a[3]), "r"(b[0]), "r"(b[1]));
}
__device__ __forceinline__ void cp16(uint32_t dst, const void* src) {
    asm volatile("cp.async.cg.shared.global [%0], [%1], 16;" :: "r"(dst), "l"(src));
}
#define CP_COMMIT() asm volatile("cp.async.commit_group;" ::: "memory")
#define CP_WAIT(n)  asm volatile("cp.async.wait_group %0;" :: "n"(n) : "memory")

// ================= 0. bf16 casts (x + 4 weights, one launch) =================
// total elems: NN*DD (x) + 4*DD*DD (weights) = 1048576 + 262144 = 1310720
__global__ void cast_kernel(const float* __restrict__ x,
                            const float* __restrict__ Wq, const float* __restrict__ Wk,
                            const float* __restrict__ Wv, const float* __restrict__ Wo) {
    int i = (blockIdx.x * 256 + threadIdx.x) * 4;
    const float* src;
    __nv_bfloat16* dst;
    if (i < NN * DD) {
        src = x + i; dst = g_xb + i;
    } else {
        int j = i - NN * DD;
        int w = j >> 16;               // DD*DD = 65536
        int o = j & 65535;
        src = ((w == 0) ? Wq : (w == 1) ? Wk : (w == 2) ? Wv : Wo) + o;
        dst = g_Wb + w * (DD * DD) + o;
    }
    float4 v = *(const float4*)src;
    *(uint2*)dst = make_uint2(pack_bf16x2(v.x, v.y), pack_bf16x2(v.z, v.w));
}

// ================= 1. adjacency init (zero + self loops) =================
__global__ void adj_init_kernel() {
    int idx = blockIdx.x * blockDim.x + threadIdx.x;
    int n = idx >> 7, w = idx & 127;
    uint32_t v = 0;
    if (w == (n >> 5)) v = 1u << (n & 31);
    g_adj[idx] = v;
}

// ================= 2. scatter edges (undirected) =================
__global__ void edge_kernel(const int* __restrict__ ei) {
    int e = blockIdx.x * blockDim.x + threadIdx.x;
    if (e >= EE) return;
    int s = ei[e], d = ei[EE + e];
    atomicOr(&g_adj[s * NWORDS + (d >> 5)], 1u << (d & 31));
    atomicOr(&g_adj[d * NWORDS + (s >> 5)], 1u << (s & 31));
}

// ================= 3. reach-2 mask (neighbor-list form) =================
__global__ void mask_kernel() {
    int n = blockIdx.x;
    int tid = threadIdx.x;  // 128
    __shared__ uint16_t nbr[1024];
    __shared__ int cnt;
    if (tid == 0) cnt = 0;
    __syncthreads();
    // phase 1: each thread scans ONLY its own word, appends set bits
    uint32_t bits = g_adj[n * NWORDS + tid];
    while (bits) {
        int b = __ffs(bits) - 1;
        bits &= bits - 1;
        int i = atomicAdd(&cnt, 1);
        nbr[i] = (uint16_t)((tid << 5) + b);
    }
    __syncthreads();
    // phase 2: OR neighbor rows (coalesced 512B per row)
    int c = cnt;
    uint32_t acc = 0;
    for (int i = 0; i < c; i++)
        acc |= g_adj[(int)nbr[i] * NWORDS + tid];
    g_mask[n * NWORDS + tid] = acc;
}

// ================= 4. bf16 tensor-core GEMM =================
// C[M=4096, N=256] = A[4096,256]@W[256,256] + bias. CTA tile 64x128, BK=32.
template <bool FP32OUT>
__device__ __forceinline__ void gemm_core(const __nv_bfloat16* __restrict__ A,
                                          const __nv_bfloat16* __restrict__ W,
                                          const float* __restrict__ bias,
                                          void* __restrict__ Cv, float scale) {
    __shared__ __nv_bfloat16 sA[2][64 * 40];
    __shared__ __nv_bfloat16 sB[2][32 * 136];

    const int tid = threadIdx.x;
    const int wid = tid >> 5;
    const int lane = tid & 31;
    const int m0 = blockIdx.y * 64;
    const int n0 = blockIdx.x * 128;

    const uint32_t aA = smem_u32(sA);
    const uint32_t aB = smem_u32(sB);
    const char* Abase = (const char*)A + (size_t)m0 * (DD * 2);
    const char* Bbase = (const char*)W + (size_t)n0 * 2;

    {
#pragma unroll
        for (int j = 0; j < 2; j++) {
            int t = tid + j * 128;
            int r = t >> 2, c = t & 3;
            cp16(aA + r * 80 + c * 16, Abase + (size_t)r * 512 + c * 16);
        }
#pragma unroll
        for (int j = 0; j < 4; j++) {
            int t = tid + j * 128;
            int r = t >> 4, c = t & 15;
            cp16(aB + r * 272 + c * 16, Bbase + (size_t)r * 512 + c * 16);
        }
        CP_COMMIT();
    }

    float acc[16][4];
#pragma unroll
    for (int j = 0; j < 16; j++)
        acc[j][0] = acc[j][1] = acc[j][2] = acc[j][3] = 0.f;

    const int m = lane >> 3, rr = lane & 7;
    const uint32_t a_off = (uint32_t)((wid * 16 + (m & 1) * 8 + rr) * 80 + (m >> 1) * 16);
    const uint32_t b_lane = (uint32_t)(((lane >> 3) & 1) * 8 * 272 + (lane & 7) * 272 +
                                       (lane >> 4) * 16);

    for (int t = 0; t < 8; t++) {
        if (t < 7) {
            int nb = (t + 1) & 1;
            uint32_t dA = aA + (uint32_t)nb * 5120;
            uint32_t dB = aB + (uint32_t)nb * 8704;
            const char* As = Abase + (size_t)(t + 1) * 64;
            const char* Bs = Bbase + (size_t)(t + 1) * 32 * 512;
#pragma unroll
            for (int j = 0; j < 2; j++) {
                int u = tid + j * 128;
                int r = u >> 2, c = u & 3;
                cp16(dA + r * 80 + c * 16, As + (size_t)r * 512 + c * 16);
            }
#pragma unroll
            for (int j = 0; j < 4; j++) {
                int u = tid + j * 128;
                int r = u >> 4, c = u & 15;
                cp16(dB + r * 272 + c * 16, Bs + (size_t)r * 512 + c * 16);
            }
            CP_COMMIT();
            CP_WAIT(1);
        } else {
            CP_WAIT(0);
        }
        __syncthreads();

        const uint32_t bufA = aA + (uint32_t)(t & 1) * 5120;
        const uint32_t bufB = aB + (uint32_t)(t & 1) * 8704;

        uint32_t aq[2][4];
        ldsm_x4(aq[0], bufA + a_off);
        ldsm_x4(aq[1], bufA + a_off + 32);

#pragma unroll
        for (int ks = 0; ks < 2; ks++) {
#pragma unroll
            for (int j = 0; j < 8; j++) {
                uint32_t vb[4];
                ldsm_x4_t(vb, bufB + (uint32_t)(ks * 16 * 272 + j * 32) + b_lane);
                mma_bf16(acc[2 * j],     aq[ks], vb);
                mma_bf16(acc[2 * j + 1], aq[ks], vb + 2);
            }
        }
        __syncthreads();
    }

    const int gg = lane >> 2, tig = lane & 3;
    const int r0 = m0 + wid * 16 + gg;
#pragma unroll
    for (int j = 0; j < 16; j++) {
        int col = n0 + j * 8 + 2 * tig;
        float2 b2 = __ldg((const float2*)(bias + col));
        if (FP32OUT) {
            float* Cf = (float*)Cv;
            *(float2*)(Cf + (size_t)r0 * DD + col) =
                make_float2(acc[j][0] + b2.x, acc[j][1] + b2.y);
            *(float2*)(Cf + (size_t)(r0 + 8) * DD + col) =
                make_float2(acc[j][2] + b2.x, acc[j][3] + b2.y);
        } else {
            __nv_bfloat16* Cb = (__nv_bfloat16*)Cv;
            *(uint32_t*)(Cb + (size_t)r0 * DD + col) =
                pack_bf16x2((acc[j][0] + b2.x) * scale, (acc[j][1] + b2.y) * scale);
            *(uint32_t*)(Cb + (size_t)(r0 + 8) * DD + col) =
                pack_bf16x2((acc[j][2] + b2.x) * scale, (acc[j][3] + b2.y) * scale);
        }
    }
}

__global__ void __launch_bounds__(128) qkv_gemm_kernel(const float* __restrict__ bq,
                                                       const float* __restrict__ bk,
                                                       const float* __restrict__ bv) {
    int z = blockIdx.z;
    const float* bias = (z == 0) ? bq : (z == 1) ? bk : bv;
    __nv_bfloat16* C = (z == 0) ? g_Qb : (z == 1) ? g_Kb : g_Vb;
    float scale = (z == 0) ? QSCALE : 1.f;
    gemm_core<false>(g_xb, g_Wb + (size_t)z * DD * DD, bias, C, scale);
}
__global__ void __launch_bounds__(128) wo_gemm_kernel(const float* __restrict__ bo) {
    gemm_core<true>(g_attb, g_Wb + (size_t)3 * DD * DD, bo, g_tmp, 1.f);
}

// ================= 5. mma.sync attention =================
// CTA: 256 threads (8 warps), 128 queries, one head. 32 kv tiles of 128 keys.
// Row-sums accumulated on ALU/FMA pipes (bf16 pair unpack), keeping the
// HMMA pipe for the minimal 64 MMAs/warp/tile.
struct AttnSmem2 {
    __nv_bfloat16 Qs[128 * 32];       // 8192 B (64B rows)
    __nv_bfloat16 Ks[2][128 * 40];    // 2 x 10240 B
    __nv_bfloat16 Vs[2][128 * 40];    // 2 x 10240 B
};                                    // total 49152 B

__global__ void __launch_bounds__(256, 2) attn_kernel() {
    __shared__ AttnSmem2 sm;
    const int tid = threadIdx.x;
    const int wid = tid >> 5;        // 0..7
    const int lane = tid & 31;
    const int h = blockIdx.y;
    const int q0 = blockIdx.x * 128;

    const uint32_t s_q = smem_u32(sm.Qs);
    const uint32_t s_k0 = smem_u32(sm.Ks[0]);
    const uint32_t s_v0 = smem_u32(sm.Vs[0]);

    const char* ksrc = (const char*)(g_Kb + h * HD);
    const char* vsrc = (const char*)(g_Vb + h * HD);

    // ---- prologue: Q + K0/V0 via cp.async ----
    {
        const char* qsrc = (const char*)(g_Qb + (size_t)q0 * DD + h * HD);
#pragma unroll
        for (int j = 0; j < 2; j++) {
            int chunk = tid + j * 256;
            int r = chunk >> 2, c = chunk & 3;
            cp16(s_q + (uint32_t)(r * 64 + c * 16), qsrc + (size_t)r * 512 + c * 16);
        }
#pragma unroll
        for (int j = 0; j < 2; j++) {
            int chunk = tid + j * 256;
            int r = chunk >> 2, c = chunk & 3;
            uint32_t off = (uint32_t)(r * 80 + c * 16);
            size_t gs = (size_t)r * 512 + c * 16;
            cp16(s_k0 + off, ksrc + gs);
            cp16(s_v0 + off, vsrc + gs);
        }
        CP_COMMIT();
    }

    const int wq0 = wid * 16;
    const int g = lane >> 2, tig = lane & 3;
    const int row0 = q0 + wq0 + g;

    uint4 mw_lo = *(const uint4*)(g_mask + (size_t)row0 * NWORDS);
    uint4 mw_hi = *(const uint4*)(g_mask + (size_t)(row0 + 8) * NWORDS);

    CP_WAIT(0);
    __syncthreads();

    uint32_t aq[2][4];
    {
        int m = lane >> 3, rr = lane & 7;
        uint32_t base = s_q + (uint32_t)((wq0 + (m & 1) * 8 + rr) * 64 + (m >> 1) * 16);
        ldsm_x4(aq[0], base);
        ldsm_x4(aq[1], base + 32);
    }

    float o[4][4];
#pragma unroll
    for (int v = 0; v < 4; v++)
#pragma unroll
        for (int i = 0; i < 4; i++) o[v][i] = 0.f;
    float ls0 = 0.f, ls1 = 0.f;

    const uint32_t k_lane_off = (uint32_t)((lane & 7) * 80 + (lane >> 3) * 16);
    const uint32_t v_lane_off = (uint32_t)(((lane >> 3) & 1) * 8 * 80 + (lane & 7) * 80 +
                                           (lane >> 4) * 16);

    for (int t = 0; t < 32; t++) {
        int buf = t & 1;
        uint4 mw_lo_n, mw_hi_n;
        if (t < 31) {
            mw_lo_n = *(const uint4*)(g_mask + (size_t)row0 * NWORDS + (t + 1) * 4);
            mw_hi_n = *(const uint4*)(g_mask + (size_t)(row0 + 8) * NWORDS + (t + 1) * 4);
            int nb = (t + 1) & 1;
            uint32_t skb = s_k0 + (uint32_t)nb * 10240;
            uint32_t svb = s_v0 + (uint32_t)nb * 10240;
            size_t tb = (size_t)(t + 1) * 128 * 512;
#pragma unroll
            for (int j = 0; j < 2; j++) {
                int chunk = tid + j * 256;
                int r = chunk >> 2, c = chunk & 3;
                uint32_t off = (uint32_t)(r * 80 + c * 16);
                size_t gs = tb + (size_t)r * 512 + c * 16;
                cp16(skb + off, ksrc + gs);
                cp16(svb + off, vsrc + gs);
            }
            CP_COMMIT();
            CP_WAIT(1);
        } else {
            CP_WAIT(0);
        }
        __syncthreads();

        const uint32_t kb_base = s_k0 + (uint32_t)buf * 10240;
        const uint32_t vb_base = s_v0 + (uint32_t)buf * 10240;
        const uint32_t mwl[4] = {mw_lo.x, mw_lo.y, mw_lo.z, mw_lo.w};
        const uint32_t mwh[4] = {mw_hi.x, mw_hi.y, mw_hi.z, mw_hi.w};

        uint32_t ap[8][4];
#pragma unroll
        for (int qd = 0; qd < 4; qd++) {
            uint32_t kb[4][4];
#pragma unroll
            for (int nt = 0; nt < 4; nt++)
                ldsm_x4(kb[nt], kb_base + (uint32_t)((qd * 4 + nt) * (8 * 80)) + k_lane_off);
            float c4[4][4];
#pragma unroll
            for (int nt = 0; nt < 4; nt++) {
                c4[nt][0] = c4[nt][1] = c4[nt][2] = c4[nt][3] = 0.f;
                mma_bf16(c4[nt], aq[0], kb[nt]);
                mma_bf16(c4[nt], aq[1], kb[nt] + 2);
            }
            uint32_t w0 = mwl[qd] >> (2 * tig);
            uint32_t w1 = mwh[qd] >> (2 * tig);
#pragma unroll
            for (int nt = 0; nt < 4; nt++) {
                uint32_t b0 = w0 >> (nt * 8), b1 = w1 >> (nt * 8);
                uint32_t m01 = ((b0 & 1u) ? 0x0000FFFFu : 0u) | ((b0 & 2u) ? 0xFFFF0000u : 0u);
                uint32_t m23 = ((b1 & 1u) ? 0x0000FFFFu : 0u) | ((b1 & 2u) ? 0xFFFF0000u : 0u);
                uint32_t p01 = ex2_bf16x2(pack_bf16x2(c4[nt][0], c4[nt][1])) & m01;
                uint32_t p23 = ex2_bf16x2(pack_bf16x2(c4[nt][2], c4[nt][3])) & m23;
                // row sums on ALU/FMA pipes (bf16->f32 via shift/mask)
                ls0 += __uint_as_float(p01 << 16) + __uint_as_float(p01 & 0xFFFF0000u);
                ls1 += __uint_as_float(p23 << 16) + __uint_as_float(p23 & 0xFFFF0000u);
                int nth = qd * 4 + nt;
                ap[nth >> 1][(nth & 1) * 2 + 0] = p01;
                ap[nth >> 1][(nth & 1) * 2 + 1] = p23;
            }
        }

        // ---- O += P @ V ----
#pragma unroll
        for (int kt = 0; kt < 8; kt++) {
            uint32_t vb[4];
            uint32_t base = vb_base + (uint32_t)kt * (16 * 80) + v_lane_off;
            ldsm_x4_t(vb, base);
            mma_bf16(o[0], ap[kt], vb);
            mma_bf16(o[1], ap[kt], vb + 2);
            ldsm_x4_t(vb, base + 32);
            mma_bf16(o[2], ap[kt], vb);
            mma_bf16(o[3], ap[kt], vb + 2);
        }

        if (t < 31) { mw_lo = mw_lo_n; mw_hi = mw_hi_n; }
        __syncthreads();
    }

    // quad-reduce row sums (cols spread over tig lanes)
    ls0 += __shfl_xor_sync(0xFFFFFFFFu, ls0, 1);
    ls0 += __shfl_xor_sync(0xFFFFFFFFu, ls0, 2);
    ls1 += __shfl_xor_sync(0xFFFFFFFFu, ls1, 1);
    ls1 += __shfl_xor_sync(0xFFFFFFFFu, ls1, 2);
    float inv0 = 1.f / ls0, inv1 = 1.f / ls1;

    __nv_bfloat16* dst0 = g_attb + (size_t)row0 * DD + h * HD + 2 * tig;
    __nv_bfloat16* dst1 = dst0 + 8 * DD;
#pragma unroll
    for (int v = 0; v < 4; v++) {
        *(uint32_t*)(dst0 + v * 8) = pack_bf16x2(o[v][0] * inv0, o[v][1] * inv0);
        *(uint32_t*)(dst1 + v * 8) = pack_bf16x2(o[v][2] * inv1, o[v][3] * inv1);
    }
}

// ================= 6. residual + LayerNorm (warp-shuffle) =================
__global__ void ln_kernel(const float* __restrict__ tmp,
                          const float* __restrict__ x,
                          const float* __restrict__ w,
                          const float* __restrict__ b,
                          float* __restrict__ out) {
    int n = blockIdx.x;
    int tid = threadIdx.x;  // 256 == DD
    int wid = tid >> 5, lane = tid & 31;
    float v = tmp[n * DD + tid] + x[n * DD + tid];
    float s1 = v, s2 = v * v;
#pragma unroll
    for (int o = 16; o > 0; o >>= 1) {
        s1 += __shfl_xor_sync(0xFFFFFFFFu, s1, o);
        s2 += __shfl_xor_sync(0xFFFFFFFFu, s2, o);
    }
    __shared__ float a1[8], a2[8];
    if (lane == 0) { a1[wid] = s1; a2[wid] = s2; }
    __syncthreads();
    float t1 = 0.f, t2 = 0.f;
#pragma unroll
    for (int i = 0; i < 8; i++) { t1 += a1[i]; t2 += a2[i]; }
    float mu = t1 * (1.f / 256.f);
    float var = t2 * (1.f / 256.f) - mu * mu;
    float inv = rsqrtf(var + 1e-5f);
    out[n * DD + tid] = (v - mu) * inv * w[tid] + b[tid];
}

// ================= launch =================
extern "C" void kernel_launch(void* const* d_in, const int* in_sizes, int n_in,
                              void* d_out, int out_size) {
    const float* x   = (const float*)d_in[0];
    const int*   ei  = (const int*)d_in[1];
    const float* Wq  = (const float*)d_in[2];
    const float* bq  = (const float*)d_in[3];
    const float* Wk  = (const float*)d_in[4];
    const float* bk  = (const float*)d_in[5];
    const float* Wv  = (const float*)d_in[6];
    const float* bv  = (const float*)d_in[7];
    const float* Wo  = (const float*)d_in[8];
    const float* bo  = (const float*)d_in[9];
    const float* lnw = (const float*)d_in[10];
    const float* lnb = (const float*)d_in[11];
    float* out = (float*)d_out;

    float* gT;
    cudaGetSymbolAddress((void**)&gT, g_tmp);

    // casts + mask pipeline
    cast_kernel<<<(NN * DD + 4 * DD * DD) / 1024, 256>>>(x, Wq, Wk, Wv, Wo);
    adj_init_kernel<<<(NN * NWORDS) / 256, 256>>>();
    edge_kernel<<<EE / 256, 256>>>(ei);
    mask_kernel<<<NN, NWORDS>>>();

    // QKV projections (tensor core, bf16 out, Q pre-scaled)
    qkv_gemm_kernel<<<dim3(DD / 128, NN / 64, 3), 128>>>(bq, bk, bv);

    // tensor-core attention
    attn_kernel<<<dim3(NN / 128, HH), 256>>>();

    // output projection (tensor core, fp32 out) + residual + LN
    wo_gemm_kernel<<<dim3(DD / 128, NN / 64), 128>>>(bo);
    ln_kernel<<<NN, 256>>>(gT, x, lnw, lnb, out);
}